// round 10
// baseline (speedup 1.0000x reference)
#include <cuda_runtime.h>
#include <cuda_fp16.h>
#include <math.h>
#include <stdint.h>

#define B_SZ 2048
#define KIN  64
#define KOUT 64
#define KH   129

// Scratch (device globals: allocation-free per the rules)
__device__ __align__(256) __half2 g_Xh[(size_t)B_SZ * KH * KIN];   // [b][f][j] ~67 MB
__device__ __align__(256) __half2 g_Yh[(size_t)B_SZ * KH * KOUT];  // [b][f][i] ~67 MB
__device__ __align__(256) __half  g_Bh[(size_t)KH * 16384];        // [f][n][k] ~4.2 MB

// ===========================================================================
// helpers
// ===========================================================================
__device__ __forceinline__ uint32_t smem_to_u32(const void* p) {
    uint32_t a;
    asm("{ .reg .u64 t; cvta.to.shared.u64 t, %1; cvt.u32.u64 %0, t; }" : "=r"(a) : "l"(p));
    return a;
}
__device__ __forceinline__ void cp_async16(uint32_t dst, const void* src) {
    asm volatile("cp.async.cg.shared.global [%0], [%1], 16;" :: "r"(dst), "l"(src));
}
#define CP_COMMIT() asm volatile("cp.async.commit_group;" ::: "memory")
#define CP_WAIT1()  asm volatile("cp.async.wait_group 1;" ::: "memory")

#define LDSM_X4(r0, r1, r2, r3, addr) \
    asm volatile("ldmatrix.sync.aligned.m8n8.x4.shared.b16 {%0,%1,%2,%3}, [%4];" \
        : "=r"(r0), "=r"(r1), "=r"(r2), "=r"(r3) : "r"(addr))

#define HMMA16(d, a, b0v, b1v) \
    asm volatile("mma.sync.aligned.m16n8k16.row.col.f32.f16.f16.f32 " \
        "{%0,%1,%2,%3}, {%4,%5,%6,%7}, {%8,%9}, {%0,%1,%2,%3};" \
        : "+f"((d)[0]), "+f"((d)[1]), "+f"((d)[2]), "+f"((d)[3]) \
        : "r"((a)[0]), "r"((a)[1]), "r"((a)[2]), "r"((a)[3]), "r"(b0v), "r"(b1v))

__device__ __forceinline__ float2 cmul(float2 a, float2 b) {
    return make_float2(a.x * b.x - a.y * b.y, a.x * b.y + a.y * b.x);
}

// ===========================================================================
// Radix-2 DIF FFT machinery (constant twiddles, outputs bit-reversed)
// ===========================================================================
#define FC1 0.9238795325112867f
#define FS1 0.3826834323650898f
#define FC2 0.7071067811865476f
#define BF(i, j, cr, ci) {                                   \
    float ux = a[i].x, uy = a[i].y;                          \
    float vx = a[j].x, vy = a[j].y;                          \
    a[i].x = ux + vx; a[i].y = uy + vy;                      \
    float dx = ux - vx, dy = uy - vy;                        \
    a[j].x = dx * (cr) - dy * (ci);                          \
    a[j].y = dx * (ci) + dy * (cr); }

template<bool INV>
__device__ __forceinline__ void fft16_full(float2* a) {
    const float S = INV ? 1.0f : -1.0f;
    BF(0, 8, 1.0f, 0.0f)      BF(1, 9, FC1, S * FS1)
    BF(2, 10, FC2, S * FC2)   BF(3, 11, FS1, S * FC1)
    BF(4, 12, 0.0f, S)        BF(5, 13, -FS1, S * FC1)
    BF(6, 14, -FC2, S * FC2)  BF(7, 15, -FC1, S * FS1)
    BF(0, 4, 1.0f, 0.0f)   BF(1, 5, FC2, S * FC2)
    BF(2, 6, 0.0f, S)      BF(3, 7, -FC2, S * FC2)
    BF(8, 12, 1.0f, 0.0f)  BF(9, 13, FC2, S * FC2)
    BF(10, 14, 0.0f, S)    BF(11, 15, -FC2, S * FC2)
    BF(0, 2, 1.0f, 0.0f)   BF(1, 3, 0.0f, S)
    BF(4, 6, 1.0f, 0.0f)   BF(5, 7, 0.0f, S)
    BF(8, 10, 1.0f, 0.0f)  BF(9, 11, 0.0f, S)
    BF(12, 14, 1.0f, 0.0f) BF(13, 15, 0.0f, S)
    BF(0, 1, 1.0f, 0.0f)   BF(2, 3, 1.0f, 0.0f)
    BF(4, 5, 1.0f, 0.0f)   BF(6, 7, 1.0f, 0.0f)
    BF(8, 9, 1.0f, 0.0f)   BF(10, 11, 1.0f, 0.0f)
    BF(12, 13, 1.0f, 0.0f) BF(14, 15, 1.0f, 0.0f)
}
template<bool INV>
__device__ __forceinline__ void fft8(float2* a) {
    const float S = INV ? 1.0f : -1.0f;
    BF(0, 4, 1.0f, 0.0f)  BF(1, 5, FC2, S * FC2)
    BF(2, 6, 0.0f, S)     BF(3, 7, -FC2, S * FC2)
    BF(0, 2, 1.0f, 0.0f)  BF(1, 3, 0.0f, S)
    BF(4, 6, 1.0f, 0.0f)  BF(5, 7, 0.0f, S)
    BF(0, 1, 1.0f, 0.0f)  BF(2, 3, 1.0f, 0.0f)
    BF(4, 5, 1.0f, 0.0f)  BF(6, 7, 1.0f, 0.0f)
}
#define REV4_LIST {0, 8, 4, 12, 2, 10, 6, 14, 1, 9, 5, 13, 3, 11, 7, 15}
#define REV3_LIST {0, 4, 2, 6, 1, 5, 3, 7}

// Bank-swizzled slot layout for the 128-pt working set (float2 units)
#define QP 257
#define SLOT(q, blk, m1) ((q) * QP + ((blk) << 3) + ((m1) ^ ((blk) & 7)))
#define FFT_SMEM (2048 + 16 * QP * 8)   // 34944 B

// ---------------------------------------------------------------------------
// Kernel 1: build B_f[n][k] half (2x-expanded complex conj W)
// ---------------------------------------------------------------------------
__global__ void prep_b(const float* __restrict__ Wr, const float* __restrict__ Wi) {
    int idx = blockIdx.x * blockDim.x + threadIdx.x;
    if (idx >= KH * 16384) return;
    int k = idx & 127;
    int n = (idx >> 7) & 127;
    int f = idx >> 14;
    int j = k >> 1, p = k & 1;
    int i = n >> 1, q = n & 1;
    size_t widx = ((size_t)i * KIN + j) * KH + f;
    float v;
    if (p == 0) v = (q == 0) ? Wr[widx] : -Wi[widx];
    else        v = (q == 0) ? Wi[widx] :  Wr[widx];
    g_Bh[idx] = __float2half_rn(v);
}

// ---------------------------------------------------------------------------
// Kernel 2: forward rFFT via 128-pt complex FFT (z[m]=x[2m]+ix[2m+1]).
// ---------------------------------------------------------------------------
__global__ __launch_bounds__(256, 6) void fft_fwd(const float* __restrict__ x) {
    extern __shared__ char sm[];
    float2* tw = (float2*)(sm);
    float2* sA = (float2*)(sm + 2048);

    const int rev4[16] = REV4_LIST;
    const int rev3[8]  = REV3_LIST;
    int tid = threadIdx.x;
    {
        float s, c;
        sincospif(-(float)tid * (1.0f / 128.0f), &s, &c);
        tw[tid] = make_float2(c, s);
    }
    int b  = blockIdx.x >> 1;
    int j0 = (blockIdx.x & 1) << 5;

    // Stage A: thread (g2 = block, m1); fft16 over m2 of z[m1+8m2]
    int g2 = tid >> 3;
    int m1 = tid & 7;
    const float2* zp = (const float2*)(x + (size_t)b * 16384 + (size_t)(j0 + g2) * 256);
    float2 a[16];
#pragma unroll
    for (int m2 = 0; m2 < 16; m2++) a[m2] = zp[m1 + 8 * m2];
    __syncthreads(); // tw ready

    fft16_full<false>(a);
#pragma unroll
    for (int q = 0; q < 16; q++) {
        float2 t2 = tw[(2 * m1 * q) & 255]; // W_128^{m1 q}
        sA[SLOT(q, g2, m1)] = cmul(a[rev4[q]], t2);
    }
    __syncthreads();

    // Stage B: in-place fft8 over m1 for each (blk, q)
#pragma unroll
    for (int r = 0; r < 2; r++) {
        int tau = tid + (r << 8);
        int blk = tau >> 4;
        int q   = tau & 15;
        float2 c[8];
        {
            float2* a = c;
#pragma unroll
            for (int mm = 0; mm < 8; mm++) a[mm] = sA[SLOT(q, blk, mm)];
            fft8<false>(a);
        }
#pragma unroll
        for (int k1 = 0; k1 < 8; k1++)
            sA[SLOT(q, blk, k1)] = c[rev3[k1]];
    }
    __syncthreads();

    // Unpack + direct coalesced gmem write (lane = blk)
    for (int idx = tid; idx < 65 * 32; idx += 256) {
        int blk = idx & 31;
        int kk  = idx >> 5;
        float2 Zk = sA[SLOT(kk & 15, blk, kk >> 4)];
        int km = (128 - kk) & 127;
        float2 Zm = sA[SLOT(km & 15, blk, km >> 4)];
        float2 E = make_float2(0.5f * (Zk.x + Zm.x), 0.5f * (Zk.y - Zm.y));
        float2 O = make_float2(0.5f * (Zk.y + Zm.y), -0.5f * (Zk.x - Zm.x));
        float2 P = cmul(O, tw[kk]);
        g_Xh[((size_t)b * KH + kk) * KIN + j0 + blk] =
            __floats2half2_rn(E.x + P.x, E.y + P.y);
        g_Xh[((size_t)b * KH + (128 - kk)) * KIN + j0 + blk] =
            __floats2half2_rn(E.x - P.x, P.y - E.y);
    }
}

// ---------------------------------------------------------------------------
// Kernel 3: pipelined fp16 mma.sync GEMM. 2 CTAs per f (8 b-tiles each);
// staged coalesced epilogue through the consumed A buffer.
// ---------------------------------------------------------------------------
#define SMB   0
#define SMA0  (128 * 272)
#define SMA1  (2 * 128 * 272)
#define SMTOT (3 * 128 * 272)

__global__ __launch_bounds__(256, 2) void cgemm_h() {
    extern __shared__ char smem[];
    uint32_t sb = smem_to_u32(smem);
    int f    = blockIdx.x;
    int half = blockIdx.y;
    int tid  = threadIdx.x;

    {
        int r = tid & 127, h = tid >> 7;
        const char* src = (const char*)(g_Bh + (size_t)f * 16384) + r * 256 + h * 128;
        uint32_t dst = sb + SMB + r * 272 + h * 128;
#pragma unroll
        for (int cc = 0; cc < 8; cc++) cp_async16(dst + cc * 16, src + cc * 16);
    }

    auto loadA = [&](int gt, int buf) {   // gt = global b-tile index
        int r = tid & 127, h = tid >> 7;
        const char* src = (const char*)(g_Xh + ((size_t)(gt * 128 + r) * KH + f) * KIN) + h * 128;
        uint32_t dst = sb + (buf ? SMA1 : SMA0) + r * 272 + h * 128;
#pragma unroll
        for (int cc = 0; cc < 8; cc++) cp_async16(dst + cc * 16, src + cc * 16);
    };

    int gt0 = half << 3;
    loadA(gt0, 0);
    CP_COMMIT();

    int lane = tid & 31, warp = tid >> 5;
    int wm = warp & 3;
    int wn = warp >> 2;

    int arow = wm * 32 + (lane & 15);
    int acol2 = ((lane >> 4) << 3) * 2;
    uint32_t aoff0 = (uint32_t)(arow * 272 + acol2);
    uint32_t aoff1 = (uint32_t)((arow + 16) * 272 + acol2);
    int brow = wn * 64 + (lane & 7) + ((lane >> 4) << 3);
    int bcol2 = (((lane >> 3) & 1) << 3) * 2;
    uint32_t boff0 = (uint32_t)(brow * 272 + bcol2);

    const int l4 = lane >> 2, lm = lane & 3;

    for (int it = 0; it < 8; it++) {
        if (it + 1 < 8) loadA(gt0 + it + 1, (it + 1) & 1);
        CP_COMMIT();
        CP_WAIT1();
        __syncthreads();

        uint32_t abase = sb + ((it & 1) ? SMA1 : SMA0);
        uint32_t bbase = sb + SMB;

        float acc[2][8][4];
#pragma unroll
        for (int mt = 0; mt < 2; mt++)
#pragma unroll
            for (int nt = 0; nt < 8; nt++)
#pragma unroll
                for (int r = 0; r < 4; r++) acc[mt][nt][r] = 0.f;

#pragma unroll
        for (int s = 0; s < 8; s++) {
            uint32_t kb = (uint32_t)s * 32;
            uint32_t a0[4], a1[4];
            LDSM_X4(a0[0], a0[1], a0[2], a0[3], abase + aoff0 + kb);
            LDSM_X4(a1[0], a1[1], a1[2], a1[3], abase + aoff1 + kb);
#pragma unroll
            for (int np = 0; np < 4; np++) {
                uint32_t b0, b1, b2, b3;
                LDSM_X4(b0, b1, b2, b3, bbase + boff0 + (uint32_t)np * (16 * 272) + kb);
                HMMA16(acc[0][np * 2],     a0, b0, b1);
                HMMA16(acc[1][np * 2],     a1, b0, b1);
                HMMA16(acc[0][np * 2 + 1], a0, b2, b3);
                HMMA16(acc[1][np * 2 + 1], a1, b2, b3);
            }
        }
        __syncthreads(); // all LDSM reads of A buffer done before staging into it

        // Stage epilogue into the consumed A buffer (272B pitch, conflict-free)
        {
            char* stg = smem + ((it & 1) ? SMA1 : SMA0);
#pragma unroll
            for (int mt = 0; mt < 2; mt++) {
                int mrow = wm * 32 + mt * 16 + l4;
#pragma unroll
                for (int nt = 0; nt < 8; nt++) {
                    int i = wn * 32 + nt * 4 + lm;
                    *(__half2*)(stg + mrow * 272 + i * 4) =
                        __floats2half2_rn(acc[mt][nt][0], acc[mt][nt][1]);
                    *(__half2*)(stg + (mrow + 8) * 272 + i * 4) =
                        __floats2half2_rn(acc[mt][nt][2], acc[mt][nt][3]);
                }
            }
        }
        __syncthreads();

        // Cooperative coalesced write: 128 rows x 256B, 2 threads per row
        {
            int row = tid >> 1;
            int hh  = tid & 1;
            const char* src = smem + ((it & 1) ? SMA1 : SMA0) + row * 272 + hh * 128;
            __half2* dst = g_Yh + ((size_t)((gt0 + it) * 128 + row) * KH + f) * KOUT + hh * 32;
#pragma unroll
            for (int c = 0; c < 8; c++) {
                float4 v = *(const float4*)(src + c * 16);
                *(float4*)(dst + c * 4) = v;
            }
        }
        __syncthreads(); // staging reads done before next cp.async overwrites
    }
}

// ---------------------------------------------------------------------------
// Kernel 4: inverse rFFT via 128-pt complex IFFT; direct gmem in AND out.
// ---------------------------------------------------------------------------
__global__ __launch_bounds__(256, 6) void fft_inv(float* __restrict__ out) {
    extern __shared__ char sm[];
    float2* tw = (float2*)(sm);
    float2* sZ = (float2*)(sm + 2048);

    const int rev4[16] = REV4_LIST;
    const int rev3[8]  = REV3_LIST;
    int tid = threadIdx.x;
    {
        float s, c;
        sincospif(-(float)tid * (1.0f / 128.0f), &s, &c);
        tw[tid] = make_float2(c, s);
    }
    int b  = blockIdx.x >> 1;
    int i0 = (blockIdx.x & 1) << 5;
    __syncthreads(); // tw ready

    // Phase 1: read Y directly from gmem (lane = ig, coalesced) and pack
    for (int idx = tid; idx < 65 * 32; idx += 256) {
        int ig = idx & 31;
        int kk = idx >> 5;
        float2 Yk = __half22float2(g_Yh[((size_t)b * KH + kk) * KOUT + i0 + ig]);
        float2 Ym = __half22float2(g_Yh[((size_t)b * KH + (128 - kk)) * KOUT + i0 + ig]);
        float2 E  = make_float2(0.5f * (Yk.x + Ym.x), 0.5f * (Yk.y - Ym.y));
        float2 O2 = make_float2(0.5f * (Yk.x - Ym.x), 0.5f * (Yk.y + Ym.y));
        float2 Wc = tw[kk];
        float2 Q  = cmul(O2, make_float2(Wc.x, -Wc.y));
        sZ[SLOT(kk & 15, ig, kk >> 4)] = make_float2(E.x - Q.y, E.y + Q.x);
        if (kk) {
            int k2 = 128 - kk;
            sZ[SLOT(k2 & 15, ig, k2 >> 4)] = make_float2(E.x + Q.y, Q.x - E.y);
        }
    }
    __syncthreads();

    // Phase 2: in-place inverse fft8 over k1 + twiddle W_128^{-m1 q}
#pragma unroll
    for (int r = 0; r < 2; r++) {
        int tau = tid + (r << 8);
        int ig = tau >> 4;
        int q  = tau & 15;
        float2 c[8];
        {
            float2* a = c;
#pragma unroll
            for (int k1 = 0; k1 < 8; k1++) a[k1] = sZ[SLOT(q, ig, k1)];
            fft8<true>(a);
        }
#pragma unroll
        for (int mm = 0; mm < 8; mm++) {
            float2 t2 = tw[(2 * mm * q) & 255];
            sZ[SLOT(q, ig, mm)] = cmul(c[rev3[mm]], make_float2(t2.x, -t2.y));
        }
    }
    __syncthreads();

    // Phase 3: inverse fft16 over q; thread = (ig, m1); direct float2 output
    {
        int ig = tid >> 3;
        int m1 = tid & 7;
        float2 a[16];
#pragma unroll
        for (int q = 0; q < 16; q++) a[q] = sZ[SLOT(q, ig, m1)];
        fft16_full<true>(a);

        float2* op = (float2*)(out + (size_t)b * 16384 + (size_t)(i0 + ig) * 256);
#pragma unroll
        for (int m2 = 0; m2 < 16; m2++) {
            float2 v = a[rev4[m2]];
            op[m1 + 8 * m2] = make_float2(v.x * (1.0f / 128.0f), v.y * (1.0f / 128.0f));
        }
    }
}

// ---------------------------------------------------------------------------
extern "C" void kernel_launch(void* const* d_in, const int* in_sizes, int n_in,
                              void* d_out, int out_size) {
    const float* x  = (const float*)d_in[0];
    const float* Wr = (const float*)d_in[1];
    const float* Wi = (const float*)d_in[2];
    float* out = (float*)d_out;

    cudaFuncSetAttribute(cgemm_h, cudaFuncAttributeMaxDynamicSharedMemorySize, SMTOT);
    cudaFuncSetAttribute(fft_fwd, cudaFuncAttributeMaxDynamicSharedMemorySize, FFT_SMEM);
    cudaFuncSetAttribute(fft_inv, cudaFuncAttributeMaxDynamicSharedMemorySize, FFT_SMEM);

    prep_b<<<(KH * 16384 + 255) / 256, 256>>>(Wr, Wi);
    fft_fwd<<<B_SZ * 2, 256, FFT_SMEM>>>(x);
    cgemm_h<<<dim3(KH, 2), 256, SMTOT>>>();
    fft_inv<<<B_SZ * 2, 256, FFT_SMEM>>>(out);
}

// round 11
// speedup vs baseline: 1.1047x; 1.1047x over previous
#include <cuda_runtime.h>
#include <cuda_fp16.h>
#include <math.h>
#include <stdint.h>

#define B_SZ 2048
#define KIN  64
#define KOUT 64
#define KH   129

// Scratch (device globals: allocation-free per the rules)
__device__ __align__(256) __half2 g_Xh[(size_t)B_SZ * KH * KIN];   // [b][f][j] ~67 MB
__device__ __align__(256) __half2 g_Yh[(size_t)B_SZ * KH * KOUT];  // [b][f][i] ~67 MB
__device__ __align__(256) __half  g_Bh[(size_t)KH * 16384];        // [f][n][k] ~4.2 MB

// ===========================================================================
// helpers
// ===========================================================================
__device__ __forceinline__ uint32_t smem_to_u32(const void* p) {
    uint32_t a;
    asm("{ .reg .u64 t; cvta.to.shared.u64 t, %1; cvt.u32.u64 %0, t; }" : "=r"(a) : "l"(p));
    return a;
}
__device__ __forceinline__ void cp_async16(uint32_t dst, const void* src) {
    asm volatile("cp.async.cg.shared.global [%0], [%1], 16;" :: "r"(dst), "l"(src));
}
#define CP_COMMIT() asm volatile("cp.async.commit_group;" ::: "memory")
#define CP_WAIT1()  asm volatile("cp.async.wait_group 1;" ::: "memory")

#define LDSM_X4(r0, r1, r2, r3, addr) \
    asm volatile("ldmatrix.sync.aligned.m8n8.x4.shared.b16 {%0,%1,%2,%3}, [%4];" \
        : "=r"(r0), "=r"(r1), "=r"(r2), "=r"(r3) : "r"(addr))

#define HMMA16(d, a, b0v, b1v) \
    asm volatile("mma.sync.aligned.m16n8k16.row.col.f32.f16.f16.f32 " \
        "{%0,%1,%2,%3}, {%4,%5,%6,%7}, {%8,%9}, {%0,%1,%2,%3};" \
        : "+f"((d)[0]), "+f"((d)[1]), "+f"((d)[2]), "+f"((d)[3]) \
        : "r"((a)[0]), "r"((a)[1]), "r"((a)[2]), "r"((a)[3]), "r"(b0v), "r"(b1v))

__device__ __forceinline__ float2 cmul(float2 a, float2 b) {
    return make_float2(a.x * b.x - a.y * b.y, a.x * b.y + a.y * b.x);
}

// ===========================================================================
// Radix-2 DIF FFT machinery (constant twiddles, outputs bit-reversed)
// ===========================================================================
#define FC1 0.9238795325112867f
#define FS1 0.3826834323650898f
#define FC2 0.7071067811865476f
#define BF(i, j, cr, ci) {                                   \
    float ux = a[i].x, uy = a[i].y;                          \
    float vx = a[j].x, vy = a[j].y;                          \
    a[i].x = ux + vx; a[i].y = uy + vy;                      \
    float dx = ux - vx, dy = uy - vy;                        \
    a[j].x = dx * (cr) - dy * (ci);                          \
    a[j].y = dx * (ci) + dy * (cr); }

template<bool INV>
__device__ __forceinline__ void fft16_full(float2* a) {
    const float S = INV ? 1.0f : -1.0f;
    BF(0, 8, 1.0f, 0.0f)      BF(1, 9, FC1, S * FS1)
    BF(2, 10, FC2, S * FC2)   BF(3, 11, FS1, S * FC1)
    BF(4, 12, 0.0f, S)        BF(5, 13, -FS1, S * FC1)
    BF(6, 14, -FC2, S * FC2)  BF(7, 15, -FC1, S * FS1)
    BF(0, 4, 1.0f, 0.0f)   BF(1, 5, FC2, S * FC2)
    BF(2, 6, 0.0f, S)      BF(3, 7, -FC2, S * FC2)
    BF(8, 12, 1.0f, 0.0f)  BF(9, 13, FC2, S * FC2)
    BF(10, 14, 0.0f, S)    BF(11, 15, -FC2, S * FC2)
    BF(0, 2, 1.0f, 0.0f)   BF(1, 3, 0.0f, S)
    BF(4, 6, 1.0f, 0.0f)   BF(5, 7, 0.0f, S)
    BF(8, 10, 1.0f, 0.0f)  BF(9, 11, 0.0f, S)
    BF(12, 14, 1.0f, 0.0f) BF(13, 15, 0.0f, S)
    BF(0, 1, 1.0f, 0.0f)   BF(2, 3, 1.0f, 0.0f)
    BF(4, 5, 1.0f, 0.0f)   BF(6, 7, 1.0f, 0.0f)
    BF(8, 9, 1.0f, 0.0f)   BF(10, 11, 1.0f, 0.0f)
    BF(12, 13, 1.0f, 0.0f) BF(14, 15, 1.0f, 0.0f)
}
template<bool INV>
__device__ __forceinline__ void fft8(float2* a) {
    const float S = INV ? 1.0f : -1.0f;
    BF(0, 4, 1.0f, 0.0f)  BF(1, 5, FC2, S * FC2)
    BF(2, 6, 0.0f, S)     BF(3, 7, -FC2, S * FC2)
    BF(0, 2, 1.0f, 0.0f)  BF(1, 3, 0.0f, S)
    BF(4, 6, 1.0f, 0.0f)  BF(5, 7, 0.0f, S)
    BF(0, 1, 1.0f, 0.0f)  BF(2, 3, 1.0f, 0.0f)
    BF(4, 5, 1.0f, 0.0f)  BF(6, 7, 1.0f, 0.0f)
}
#define REV4_LIST {0, 8, 4, 12, 2, 10, 6, 14, 1, 9, 5, 13, 3, 11, 7, 15}
#define REV3_LIST {0, 4, 2, 6, 1, 5, 3, 7}

// Bank-swizzled slot layout for the 128-pt working set (float2 units)
#define QP 257
#define SLOT(q, blk, m1) ((q) * QP + ((blk) << 3) + ((m1) ^ ((blk) & 7)))
#define FFT_SMEM (2048 + 16 * QP * 8)   // 34944 B

// ---------------------------------------------------------------------------
// Kernel 1: build B_f[n][k] half (2x-expanded complex conj W)
// ---------------------------------------------------------------------------
__global__ void prep_b(const float* __restrict__ Wr, const float* __restrict__ Wi) {
    int idx = blockIdx.x * blockDim.x + threadIdx.x;
    if (idx >= KH * 16384) return;
    int k = idx & 127;
    int n = (idx >> 7) & 127;
    int f = idx >> 14;
    int j = k >> 1, p = k & 1;
    int i = n >> 1, q = n & 1;
    size_t widx = ((size_t)i * KIN + j) * KH + f;
    float v;
    if (p == 0) v = (q == 0) ? Wr[widx] : -Wi[widx];
    else        v = (q == 0) ? Wi[widx] :  Wr[widx];
    g_Bh[idx] = __float2half_rn(v);
}

// ---------------------------------------------------------------------------
// Kernel 2: forward rFFT via 128-pt complex FFT (z[m]=x[2m]+ix[2m+1]).
// ---------------------------------------------------------------------------
__global__ __launch_bounds__(256, 6) void fft_fwd(const float* __restrict__ x) {
    extern __shared__ char sm[];
    float2* tw = (float2*)(sm);
    float2* sA = (float2*)(sm + 2048);

    const int rev4[16] = REV4_LIST;
    const int rev3[8]  = REV3_LIST;
    int tid = threadIdx.x;
    {
        float s, c;
        sincospif(-(float)tid * (1.0f / 128.0f), &s, &c);
        tw[tid] = make_float2(c, s);
    }
    int b  = blockIdx.x >> 1;
    int j0 = (blockIdx.x & 1) << 5;

    // Stage A: thread (g2 = block, m1); fft16 over m2 of z[m1+8m2]
    int g2 = tid >> 3;
    int m1 = tid & 7;
    const float2* zp = (const float2*)(x + (size_t)b * 16384 + (size_t)(j0 + g2) * 256);
    float2 a[16];
#pragma unroll
    for (int m2 = 0; m2 < 16; m2++) a[m2] = zp[m1 + 8 * m2];
    __syncthreads(); // tw ready

    fft16_full<false>(a);
#pragma unroll
    for (int q = 0; q < 16; q++) {
        float2 t2 = tw[(2 * m1 * q) & 255]; // W_128^{m1 q}
        sA[SLOT(q, g2, m1)] = cmul(a[rev4[q]], t2);
    }
    __syncthreads();

    // Stage B: in-place fft8 over m1 for each (blk, q)
#pragma unroll
    for (int r = 0; r < 2; r++) {
        int tau = tid + (r << 8);
        int blk = tau >> 4;
        int q   = tau & 15;
        float2 c[8];
        {
            float2* a = c;
#pragma unroll
            for (int mm = 0; mm < 8; mm++) a[mm] = sA[SLOT(q, blk, mm)];
            fft8<false>(a);
        }
#pragma unroll
        for (int k1 = 0; k1 < 8; k1++)
            sA[SLOT(q, blk, k1)] = c[rev3[k1]];
    }
    __syncthreads();

    // Unpack + direct coalesced gmem write (lane = blk)
    for (int idx = tid; idx < 65 * 32; idx += 256) {
        int blk = idx & 31;
        int kk  = idx >> 5;
        float2 Zk = sA[SLOT(kk & 15, blk, kk >> 4)];
        int km = (128 - kk) & 127;
        float2 Zm = sA[SLOT(km & 15, blk, km >> 4)];
        float2 E = make_float2(0.5f * (Zk.x + Zm.x), 0.5f * (Zk.y - Zm.y));
        float2 O = make_float2(0.5f * (Zk.y + Zm.y), -0.5f * (Zk.x - Zm.x));
        float2 P = cmul(O, tw[kk]);
        g_Xh[((size_t)b * KH + kk) * KIN + j0 + blk] =
            __floats2half2_rn(E.x + P.x, E.y + P.y);
        g_Xh[((size_t)b * KH + (128 - kk)) * KIN + j0 + blk] =
            __floats2half2_rn(E.x - P.x, P.y - E.y);
    }
}

// ---------------------------------------------------------------------------
// Kernel 3: pipelined fp16 mma.sync GEMM. 4 CTAs per f (4 b-tiles each);
// staged coalesced epilogue through the consumed A buffer.
// ---------------------------------------------------------------------------
#define SMB   0
#define SMA0  (128 * 272)
#define SMA1  (2 * 128 * 272)
#define SMTOT (3 * 128 * 272)
#define NTILES 4

__global__ __launch_bounds__(256, 2) void cgemm_h() {
    extern __shared__ char smem[];
    uint32_t sb = smem_to_u32(smem);
    int f    = blockIdx.x;
    int part = blockIdx.y;
    int tid  = threadIdx.x;

    {
        int r = tid & 127, h = tid >> 7;
        const char* src = (const char*)(g_Bh + (size_t)f * 16384) + r * 256 + h * 128;
        uint32_t dst = sb + SMB + r * 272 + h * 128;
#pragma unroll
        for (int cc = 0; cc < 8; cc++) cp_async16(dst + cc * 16, src + cc * 16);
    }

    auto loadA = [&](int gt, int buf) {   // gt = global b-tile index
        int r = tid & 127, h = tid >> 7;
        const char* src = (const char*)(g_Xh + ((size_t)(gt * 128 + r) * KH + f) * KIN) + h * 128;
        uint32_t dst = sb + (buf ? SMA1 : SMA0) + r * 272 + h * 128;
#pragma unroll
        for (int cc = 0; cc < 8; cc++) cp_async16(dst + cc * 16, src + cc * 16);
    };

    int gt0 = part * NTILES;
    loadA(gt0, 0);
    CP_COMMIT();

    int lane = tid & 31, warp = tid >> 5;
    int wm = warp & 3;
    int wn = warp >> 2;

    int arow = wm * 32 + (lane & 15);
    int acol2 = ((lane >> 4) << 3) * 2;
    uint32_t aoff0 = (uint32_t)(arow * 272 + acol2);
    uint32_t aoff1 = (uint32_t)((arow + 16) * 272 + acol2);
    int brow = wn * 64 + (lane & 7) + ((lane >> 4) << 3);
    int bcol2 = (((lane >> 3) & 1) << 3) * 2;
    uint32_t boff0 = (uint32_t)(brow * 272 + bcol2);

    const int l4 = lane >> 2, lm = lane & 3;

    for (int it = 0; it < NTILES; it++) {
        if (it + 1 < NTILES) loadA(gt0 + it + 1, (it + 1) & 1);
        CP_COMMIT();
        CP_WAIT1();
        __syncthreads();

        uint32_t abase = sb + ((it & 1) ? SMA1 : SMA0);
        uint32_t bbase = sb + SMB;

        float acc[2][8][4];
#pragma unroll
        for (int mt = 0; mt < 2; mt++)
#pragma unroll
            for (int nt = 0; nt < 8; nt++)
#pragma unroll
                for (int r = 0; r < 4; r++) acc[mt][nt][r] = 0.f;

#pragma unroll
        for (int s = 0; s < 8; s++) {
            uint32_t kb = (uint32_t)s * 32;
            uint32_t a0[4], a1[4];
            LDSM_X4(a0[0], a0[1], a0[2], a0[3], abase + aoff0 + kb);
            LDSM_X4(a1[0], a1[1], a1[2], a1[3], abase + aoff1 + kb);
#pragma unroll
            for (int np = 0; np < 4; np++) {
                uint32_t b0, b1, b2, b3;
                LDSM_X4(b0, b1, b2, b3, bbase + boff0 + (uint32_t)np * (16 * 272) + kb);
                HMMA16(acc[0][np * 2],     a0, b0, b1);
                HMMA16(acc[1][np * 2],     a1, b0, b1);
                HMMA16(acc[0][np * 2 + 1], a0, b2, b3);
                HMMA16(acc[1][np * 2 + 1], a1, b2, b3);
            }
        }
        __syncthreads(); // all LDSM reads of A buffer done before staging into it

        // Stage epilogue into the consumed A buffer (272B pitch, conflict-free)
        {
            char* stg = smem + ((it & 1) ? SMA1 : SMA0);
#pragma unroll
            for (int mt = 0; mt < 2; mt++) {
                int mrow = wm * 32 + mt * 16 + l4;
#pragma unroll
                for (int nt = 0; nt < 8; nt++) {
                    int i = wn * 32 + nt * 4 + lm;
                    *(__half2*)(stg + mrow * 272 + i * 4) =
                        __floats2half2_rn(acc[mt][nt][0], acc[mt][nt][1]);
                    *(__half2*)(stg + (mrow + 8) * 272 + i * 4) =
                        __floats2half2_rn(acc[mt][nt][2], acc[mt][nt][3]);
                }
            }
        }
        __syncthreads();

        // Cooperative coalesced write: 128 rows x 256B, 2 threads per row
        {
            int row = tid >> 1;
            int hh  = tid & 1;
            const char* src = smem + ((it & 1) ? SMA1 : SMA0) + row * 272 + hh * 128;
            __half2* dst = g_Yh + ((size_t)((gt0 + it) * 128 + row) * KH + f) * KOUT + hh * 32;
#pragma unroll
            for (int c = 0; c < 8; c++) {
                float4 v = *(const float4*)(src + c * 16);
                *(float4*)(dst + c * 4) = v;
            }
        }
        __syncthreads(); // staging reads done before next cp.async overwrites
    }
}

// ---------------------------------------------------------------------------
// Kernel 4: inverse rFFT via 128-pt complex IFFT.
// Fused pack+fft8: thread (ig,q) gathers Z inputs straight from gmem,
// does fft8 in registers, one smem transpose, fft16, direct output.
// ---------------------------------------------------------------------------
__global__ __launch_bounds__(256, 6) void fft_inv(float* __restrict__ out) {
    extern __shared__ char sm[];
    float2* tw = (float2*)(sm);
    float2* sZ = (float2*)(sm + 2048);

    const int rev4[16] = REV4_LIST;
    const int rev3[8]  = REV3_LIST;
    int tid = threadIdx.x;
    {
        float s, c;
        sincospif(-(float)tid * (1.0f / 128.0f), &s, &c);
        tw[tid] = make_float2(c, s);
    }
    int b  = blockIdx.x >> 1;
    int i0 = (blockIdx.x & 1) << 5;
    const __half2* Yrow = g_Yh + (size_t)b * KH * KOUT + i0;
    __syncthreads(); // tw ready

    // Fused phase: for (ig, q): gather Z[q+16k1] from gmem, fft8, twiddle, store
#pragma unroll
    for (int r = 0; r < 2; r++) {
        int tau = tid + (r << 8);
        int ig = tau & 31;          // lane = ig -> coalesced gmem rows
        int q  = (tau >> 5) + (r ? 0 : 0); // q in 0..7 (r=0), 8..15 (r=1)
        float2 c[8];
#pragma unroll
        for (int k1 = 0; k1 < 8; k1++) {
            int k = q + (k1 << 4);
            float2 Yk = __half22float2(Yrow[(size_t)k * KOUT + ig]);
            float2 Ym = __half22float2(Yrow[(size_t)(128 - k) * KOUT + ig]);
            float2 E  = make_float2(0.5f * (Yk.x + Ym.x), 0.5f * (Yk.y - Ym.y));
            float2 O2 = make_float2(0.5f * (Yk.x - Ym.x), 0.5f * (Yk.y + Ym.y));
            float2 Wc = tw[k];
            float2 Q  = cmul(O2, make_float2(Wc.x, -Wc.y));
            c[k1] = make_float2(E.x - Q.y, E.y + Q.x);
        }
        fft8<true>(c);
#pragma unroll
        for (int mm = 0; mm < 8; mm++) {
            float2 t2 = tw[(2 * mm * q) & 255];
            sZ[SLOT(q, ig, mm)] = cmul(c[rev3[mm]], make_float2(t2.x, -t2.y));
        }
    }
    __syncthreads();

    // Final phase: inverse fft16 over q; thread = (ig, m1); direct float2 output
    {
        int ig = tid >> 3;
        int m1 = tid & 7;
        float2 a[16];
#pragma unroll
        for (int q = 0; q < 16; q++) a[q] = sZ[SLOT(q, ig, m1)];
        fft16_full<true>(a);

        float2* op = (float2*)(out + (size_t)b * 16384 + (size_t)(i0 + ig) * 256);
#pragma unroll
        for (int m2 = 0; m2 < 16; m2++) {
            float2 v = a[rev4[m2]];
            op[m1 + 8 * m2] = make_float2(v.x * (1.0f / 128.0f), v.y * (1.0f / 128.0f));
        }
    }
}

// ---------------------------------------------------------------------------
extern "C" void kernel_launch(void* const* d_in, const int* in_sizes, int n_in,
                              void* d_out, int out_size) {
    const float* x  = (const float*)d_in[0];
    const float* Wr = (const float*)d_in[1];
    const float* Wi = (const float*)d_in[2];
    float* out = (float*)d_out;

    cudaFuncSetAttribute(cgemm_h, cudaFuncAttributeMaxDynamicSharedMemorySize, SMTOT);
    cudaFuncSetAttribute(fft_fwd, cudaFuncAttributeMaxDynamicSharedMemorySize, FFT_SMEM);
    cudaFuncSetAttribute(fft_inv, cudaFuncAttributeMaxDynamicSharedMemorySize, FFT_SMEM);

    prep_b<<<(KH * 16384 + 255) / 256, 256>>>(Wr, Wi);
    fft_fwd<<<B_SZ * 2, 256, FFT_SMEM>>>(x);
    cgemm_h<<<dim3(KH, 16 / NTILES), 256, SMTOT>>>();
    fft_inv<<<B_SZ * 2, 256, FFT_SMEM>>>(out);
}

// round 12
// speedup vs baseline: 1.1811x; 1.0692x over previous
#include <cuda_runtime.h>
#include <cuda_fp16.h>
#include <math.h>
#include <stdint.h>

#define B_SZ 2048
#define KIN  64
#define KOUT 64
#define KH   129

// Scratch (device globals: allocation-free per the rules)
__device__ __align__(256) __half2 g_Xh[(size_t)B_SZ * KH * KIN];   // [b][f][j] ~67 MB
__device__ __align__(256) __half2 g_Yh[(size_t)B_SZ * KH * KOUT];  // [b][f][i] ~67 MB
__device__ __align__(256) __half  g_Bh[(size_t)KH * 16384];        // [f][n][k] ~4.2 MB

// ===========================================================================
// helpers
// ===========================================================================
__device__ __forceinline__ uint32_t smem_to_u32(const void* p) {
    uint32_t a;
    asm("{ .reg .u64 t; cvta.to.shared.u64 t, %1; cvt.u32.u64 %0, t; }" : "=r"(a) : "l"(p));
    return a;
}
__device__ __forceinline__ void cp_async16(uint32_t dst, const void* src) {
    asm volatile("cp.async.cg.shared.global [%0], [%1], 16;" :: "r"(dst), "l"(src));
}
#define CP_COMMIT() asm volatile("cp.async.commit_group;" ::: "memory")
#define CP_WAIT1()  asm volatile("cp.async.wait_group 1;" ::: "memory")

#define LDSM_X4(r0, r1, r2, r3, addr) \
    asm volatile("ldmatrix.sync.aligned.m8n8.x4.shared.b16 {%0,%1,%2,%3}, [%4];" \
        : "=r"(r0), "=r"(r1), "=r"(r2), "=r"(r3) : "r"(addr))

#define HMMA16(d, a, b0v, b1v) \
    asm volatile("mma.sync.aligned.m16n8k16.row.col.f32.f16.f16.f32 " \
        "{%0,%1,%2,%3}, {%4,%5,%6,%7}, {%8,%9}, {%0,%1,%2,%3};" \
        : "+f"((d)[0]), "+f"((d)[1]), "+f"((d)[2]), "+f"((d)[3]) \
        : "r"((a)[0]), "r"((a)[1]), "r"((a)[2]), "r"((a)[3]), "r"(b0v), "r"(b1v))

__device__ __forceinline__ float2 cmul(float2 a, float2 b) {
    return make_float2(a.x * b.x - a.y * b.y, a.x * b.y + a.y * b.x);
}

// ===========================================================================
// Radix-2 DIF FFT machinery (constant twiddles, outputs bit-reversed)
// ===========================================================================
#define FC1 0.9238795325112867f
#define FS1 0.3826834323650898f
#define FC2 0.7071067811865476f
#define BF(i, j, cr, ci) {                                   \
    float ux = a[i].x, uy = a[i].y;                          \
    float vx = a[j].x, vy = a[j].y;                          \
    a[i].x = ux + vx; a[i].y = uy + vy;                      \
    float dx = ux - vx, dy = uy - vy;                        \
    a[j].x = dx * (cr) - dy * (ci);                          \
    a[j].y = dx * (ci) + dy * (cr); }

template<bool INV>
__device__ __forceinline__ void fft16_full(float2* a) {
    const float S = INV ? 1.0f : -1.0f;
    BF(0, 8, 1.0f, 0.0f)      BF(1, 9, FC1, S * FS1)
    BF(2, 10, FC2, S * FC2)   BF(3, 11, FS1, S * FC1)
    BF(4, 12, 0.0f, S)        BF(5, 13, -FS1, S * FC1)
    BF(6, 14, -FC2, S * FC2)  BF(7, 15, -FC1, S * FS1)
    BF(0, 4, 1.0f, 0.0f)   BF(1, 5, FC2, S * FC2)
    BF(2, 6, 0.0f, S)      BF(3, 7, -FC2, S * FC2)
    BF(8, 12, 1.0f, 0.0f)  BF(9, 13, FC2, S * FC2)
    BF(10, 14, 0.0f, S)    BF(11, 15, -FC2, S * FC2)
    BF(0, 2, 1.0f, 0.0f)   BF(1, 3, 0.0f, S)
    BF(4, 6, 1.0f, 0.0f)   BF(5, 7, 0.0f, S)
    BF(8, 10, 1.0f, 0.0f)  BF(9, 11, 0.0f, S)
    BF(12, 14, 1.0f, 0.0f) BF(13, 15, 0.0f, S)
    BF(0, 1, 1.0f, 0.0f)   BF(2, 3, 1.0f, 0.0f)
    BF(4, 5, 1.0f, 0.0f)   BF(6, 7, 1.0f, 0.0f)
    BF(8, 9, 1.0f, 0.0f)   BF(10, 11, 1.0f, 0.0f)
    BF(12, 13, 1.0f, 0.0f) BF(14, 15, 1.0f, 0.0f)
}
template<bool INV>
__device__ __forceinline__ void fft8(float2* a) {
    const float S = INV ? 1.0f : -1.0f;
    BF(0, 4, 1.0f, 0.0f)  BF(1, 5, FC2, S * FC2)
    BF(2, 6, 0.0f, S)     BF(3, 7, -FC2, S * FC2)
    BF(0, 2, 1.0f, 0.0f)  BF(1, 3, 0.0f, S)
    BF(4, 6, 1.0f, 0.0f)  BF(5, 7, 0.0f, S)
    BF(0, 1, 1.0f, 0.0f)  BF(2, 3, 1.0f, 0.0f)
    BF(4, 5, 1.0f, 0.0f)  BF(6, 7, 1.0f, 0.0f)
}
#define REV4_LIST {0, 8, 4, 12, 2, 10, 6, 14, 1, 9, 5, 13, 3, 11, 7, 15}
#define REV3_LIST {0, 4, 2, 6, 1, 5, 3, 7}

// Bank-swizzled slot layout for the 128-pt working set (float2 units)
#define QP 257
#define SLOT(q, blk, m1) ((q) * QP + ((blk) << 3) + ((m1) ^ ((blk) & 7)))
#define FFT_SMEM (2048 + 16 * QP * 8)   // 34944 B

// ---------------------------------------------------------------------------
// Kernel 1: build B_f[n][k] half (2x-expanded complex conj W)
// ---------------------------------------------------------------------------
__global__ void prep_b(const float* __restrict__ Wr, const float* __restrict__ Wi) {
    int idx = blockIdx.x * blockDim.x + threadIdx.x;
    if (idx >= KH * 16384) return;
    int k = idx & 127;
    int n = (idx >> 7) & 127;
    int f = idx >> 14;
    int j = k >> 1, p = k & 1;
    int i = n >> 1, q = n & 1;
    size_t widx = ((size_t)i * KIN + j) * KH + f;
    float v;
    if (p == 0) v = (q == 0) ? Wr[widx] : -Wi[widx];
    else        v = (q == 0) ? Wi[widx] :  Wr[widx];
    g_Bh[idx] = __float2half_rn(v);
}

// ---------------------------------------------------------------------------
// Kernel 2: forward rFFT via 128-pt complex FFT (z[m]=x[2m]+ix[2m+1]).
// Fused stage-B+unpack: thread (blk, g) owns columns qa=g, qb=(g?16-g:8);
// both fft8s in registers, unpack pairs (kk,128-kk) entirely in-thread.
// ---------------------------------------------------------------------------
__global__ __launch_bounds__(256, 4) void fft_fwd(const float* __restrict__ x) {
    extern __shared__ char sm[];
    float2* tw = (float2*)(sm);
    float2* sA = (float2*)(sm + 2048);

    const int rev4[16] = REV4_LIST;
    const int rev3[8]  = REV3_LIST;
    int tid = threadIdx.x;
    {
        float s, c;
        sincospif(-(float)tid * (1.0f / 128.0f), &s, &c);
        tw[tid] = make_float2(c, s);
    }
    int b  = blockIdx.x >> 1;
    int j0 = (blockIdx.x & 1) << 5;

    // Stage A: thread (g2 = block, m1); fft16 over m2 of z[m1+8m2]
    int g2 = tid >> 3;
    int m1 = tid & 7;
    const float2* zp = (const float2*)(x + (size_t)b * 16384 + (size_t)(j0 + g2) * 256);
    float2 a[16];
#pragma unroll
    for (int m2 = 0; m2 < 16; m2++) a[m2] = zp[m1 + 8 * m2];
    __syncthreads(); // tw ready

    fft16_full<false>(a);
#pragma unroll
    for (int q = 0; q < 16; q++) {
        float2 t2 = tw[(2 * m1 * q) & 255]; // W_128^{m1 q}
        sA[SLOT(q, g2, m1)] = cmul(a[rev4[q]], t2);
    }
    __syncthreads();

    // Fused: thread (blk = lane, g = warp): columns qa=g, qb=(g?16-g:8)
    int blk = tid & 31;
    int g   = tid >> 5;
    int qa = g;
    int qb = g ? (16 - g) : 8;

    float2 ca[8], cb[8];
#pragma unroll
    for (int mm = 0; mm < 8; mm++) ca[mm] = sA[SLOT(qa, blk, mm)];
#pragma unroll
    for (int mm = 0; mm < 8; mm++) cb[mm] = sA[SLOT(qb, blk, mm)];
    fft8<false>(ca);   // Z[qa + 16 k1] = ca[rev3[k1]]
    fft8<false>(cb);   // Z[qb + 16 k1] = cb[rev3[k1]]

    __half2* Xcol = g_Xh + (size_t)b * KH * KIN + j0 + blk;
    auto unpack = [&](int kk, float2 Zk, float2 Zm) {
        float2 E = make_float2(0.5f * (Zk.x + Zm.x), 0.5f * (Zk.y - Zm.y));
        float2 O = make_float2(0.5f * (Zk.y + Zm.y), -0.5f * (Zk.x - Zm.x));
        float2 P = cmul(O, tw[kk]);
        Xcol[(size_t)kk * KIN]         = __floats2half2_rn(E.x + P.x, E.y + P.y);
        Xcol[(size_t)(128 - kk) * KIN] = __floats2half2_rn(E.x - P.x, P.y - E.y);
    };

    if (g == 0) {
        // qa = 0: kk = 16t (t=0..4); Zm index: t==0 -> 0, else 8-t
        unpack(0, ca[0], ca[0]);
#pragma unroll
        for (int t = 1; t < 4; t++) unpack(16 * t, ca[rev3[t]], ca[rev3[8 - t]]);
        unpack(64, ca[rev3[4]], ca[rev3[4]]);
        // qb = 8: self-paired: km = 8 + 16(7-t)
#pragma unroll
        for (int t = 0; t < 4; t++) unpack(8 + 16 * t, cb[rev3[t]], cb[rev3[7 - t]]);
    } else {
        // kk = qa+16t pairs with column qb at index 7-t, and vice versa
#pragma unroll
        for (int t = 0; t < 4; t++) {
            unpack(qa + 16 * t, ca[rev3[t]], cb[rev3[7 - t]]);
            unpack(qb + 16 * t, cb[rev3[t]], ca[rev3[7 - t]]);
        }
    }
}

// ---------------------------------------------------------------------------
// Kernel 3: pipelined fp16 mma.sync GEMM. 4 CTAs per f (4 b-tiles each);
// direct epilogue (L2 combines the 16B quad segments), 2 syncs per tile.
// ---------------------------------------------------------------------------
#define SMB   0
#define SMA0  (128 * 272)
#define SMA1  (2 * 128 * 272)
#define SMTOT (3 * 128 * 272)
#define NTILES 4

__global__ __launch_bounds__(256, 2) void cgemm_h() {
    extern __shared__ char smem[];
    uint32_t sb = smem_to_u32(smem);
    int f    = blockIdx.x;
    int part = blockIdx.y;
    int tid  = threadIdx.x;

    {
        int r = tid & 127, h = tid >> 7;
        const char* src = (const char*)(g_Bh + (size_t)f * 16384) + r * 256 + h * 128;
        uint32_t dst = sb + SMB + r * 272 + h * 128;
#pragma unroll
        for (int cc = 0; cc < 8; cc++) cp_async16(dst + cc * 16, src + cc * 16);
    }

    auto loadA = [&](int gt, int buf) {   // gt = global b-tile index
        int r = tid & 127, h = tid >> 7;
        const char* src = (const char*)(g_Xh + ((size_t)(gt * 128 + r) * KH + f) * KIN) + h * 128;
        uint32_t dst = sb + (buf ? SMA1 : SMA0) + r * 272 + h * 128;
#pragma unroll
        for (int cc = 0; cc < 8; cc++) cp_async16(dst + cc * 16, src + cc * 16);
    };

    int gt0 = part * NTILES;
    loadA(gt0, 0);
    CP_COMMIT();

    int lane = tid & 31, warp = tid >> 5;
    int wm = warp & 3;
    int wn = warp >> 2;

    int arow = wm * 32 + (lane & 15);
    int acol2 = ((lane >> 4) << 3) * 2;
    uint32_t aoff0 = (uint32_t)(arow * 272 + acol2);
    uint32_t aoff1 = (uint32_t)((arow + 16) * 272 + acol2);
    int brow = wn * 64 + (lane & 7) + ((lane >> 4) << 3);
    int bcol2 = (((lane >> 3) & 1) << 3) * 2;
    uint32_t boff0 = (uint32_t)(brow * 272 + bcol2);

    const int l4 = lane >> 2, lm = lane & 3;

    for (int it = 0; it < NTILES; it++) {
        if (it + 1 < NTILES) loadA(gt0 + it + 1, (it + 1) & 1);
        CP_COMMIT();
        CP_WAIT1();
        __syncthreads();

        uint32_t abase = sb + ((it & 1) ? SMA1 : SMA0);
        uint32_t bbase = sb + SMB;

        float acc[2][8][4];
#pragma unroll
        for (int mt = 0; mt < 2; mt++)
#pragma unroll
            for (int nt = 0; nt < 8; nt++)
#pragma unroll
                for (int r = 0; r < 4; r++) acc[mt][nt][r] = 0.f;

#pragma unroll
        for (int s = 0; s < 8; s++) {
            uint32_t kb = (uint32_t)s * 32;
            uint32_t a0[4], a1[4];
            LDSM_X4(a0[0], a0[1], a0[2], a0[3], abase + aoff0 + kb);
            LDSM_X4(a1[0], a1[1], a1[2], a1[3], abase + aoff1 + kb);
#pragma unroll
            for (int np = 0; np < 4; np++) {
                uint32_t b0, b1, b2, b3;
                LDSM_X4(b0, b1, b2, b3, bbase + boff0 + (uint32_t)np * (16 * 272) + kb);
                HMMA16(acc[0][np * 2],     a0, b0, b1);
                HMMA16(acc[1][np * 2],     a1, b0, b1);
                HMMA16(acc[0][np * 2 + 1], a0, b2, b3);
                HMMA16(acc[1][np * 2 + 1], a1, b2, b3);
            }
        }

        // Direct epilogue: half2 complex writes (sector-combined by L2)
        int b0r = (gt0 + it) * 128;
#pragma unroll
        for (int mt = 0; mt < 2; mt++) {
            int mrow = wm * 32 + mt * 16 + l4;
            size_t base0 = ((size_t)(b0r + mrow) * KH + f) * KOUT;
            size_t base1 = base0 + (size_t)8 * KH * KOUT;
#pragma unroll
            for (int nt = 0; nt < 8; nt++) {
                int i = wn * 32 + nt * 4 + lm;
                g_Yh[base0 + i] = __floats2half2_rn(acc[mt][nt][0], acc[mt][nt][1]);
                g_Yh[base1 + i] = __floats2half2_rn(acc[mt][nt][2], acc[mt][nt][3]);
            }
        }
        __syncthreads(); // A buffer fully consumed before it is refilled
    }
}

// ---------------------------------------------------------------------------
// Kernel 4: inverse rFFT via 128-pt complex IFFT (fused pack+fft8).
// ---------------------------------------------------------------------------
__global__ __launch_bounds__(256, 6) void fft_inv(float* __restrict__ out) {
    extern __shared__ char sm[];
    float2* tw = (float2*)(sm);
    float2* sZ = (float2*)(sm + 2048);

    const int rev4[16] = REV4_LIST;
    const int rev3[8]  = REV3_LIST;
    int tid = threadIdx.x;
    {
        float s, c;
        sincospif(-(float)tid * (1.0f / 128.0f), &s, &c);
        tw[tid] = make_float2(c, s);
    }
    int b  = blockIdx.x >> 1;
    int i0 = (blockIdx.x & 1) << 5;
    const __half2* Yrow = g_Yh + (size_t)b * KH * KOUT + i0;
    __syncthreads(); // tw ready

    // Fused phase: for (ig, q): gather Z[q+16k1] from gmem, fft8, twiddle, store
#pragma unroll
    for (int r = 0; r < 2; r++) {
        int tau = tid + (r << 8);
        int ig = tau & 31;          // lane = ig -> coalesced gmem rows
        int q  = tau >> 5;
        float2 c[8];
#pragma unroll
        for (int k1 = 0; k1 < 8; k1++) {
            int k = q + (k1 << 4);
            float2 Yk = __half22float2(Yrow[(size_t)k * KOUT + ig]);
            float2 Ym = __half22float2(Yrow[(size_t)(128 - k) * KOUT + ig]);
            float2 E  = make_float2(0.5f * (Yk.x + Ym.x), 0.5f * (Yk.y - Ym.y));
            float2 O2 = make_float2(0.5f * (Yk.x - Ym.x), 0.5f * (Yk.y + Ym.y));
            float2 Wc = tw[k];
            float2 Q  = cmul(O2, make_float2(Wc.x, -Wc.y));
            c[k1] = make_float2(E.x - Q.y, E.y + Q.x);
        }
        fft8<true>(c);
#pragma unroll
        for (int mm = 0; mm < 8; mm++) {
            float2 t2 = tw[(2 * mm * q) & 255];
            sZ[SLOT(q, ig, mm)] = cmul(c[rev3[mm]], make_float2(t2.x, -t2.y));
        }
    }
    __syncthreads();

    // Final phase: inverse fft16 over q; thread = (ig, m1); direct float2 output
    {
        int ig = tid >> 3;
        int m1 = tid & 7;
        float2 a[16];
#pragma unroll
        for (int q = 0; q < 16; q++) a[q] = sZ[SLOT(q, ig, m1)];
        fft16_full<true>(a);

        float2* op = (float2*)(out + (size_t)b * 16384 + (size_t)(i0 + ig) * 256);
#pragma unroll
        for (int m2 = 0; m2 < 16; m2++) {
            float2 v = a[rev4[m2]];
            op[m1 + 8 * m2] = make_float2(v.x * (1.0f / 128.0f), v.y * (1.0f / 128.0f));
        }
    }
}

// ---------------------------------------------------------------------------
extern "C" void kernel_launch(void* const* d_in, const int* in_sizes, int n_in,
                              void* d_out, int out_size) {
    const float* x  = (const float*)d_in[0];
    const float* Wr = (const float*)d_in[1];
    const float* Wi = (const float*)d_in[2];
    float* out = (float*)d_out;

    cudaFuncSetAttribute(cgemm_h, cudaFuncAttributeMaxDynamicSharedMemorySize, SMTOT);
    cudaFuncSetAttribute(fft_fwd, cudaFuncAttributeMaxDynamicSharedMemorySize, FFT_SMEM);
    cudaFuncSetAttribute(fft_inv, cudaFuncAttributeMaxDynamicSharedMemorySize, FFT_SMEM);

    prep_b<<<(KH * 16384 + 255) / 256, 256>>>(Wr, Wi);
    fft_fwd<<<B_SZ * 2, 256, FFT_SMEM>>>(x);
    cgemm_h<<<dim3(KH, 16 / NTILES), 256, SMTOT>>>();
    fft_inv<<<B_SZ * 2, 256, FFT_SMEM>>>(out);
}

// round 13
// speedup vs baseline: 1.2285x; 1.0401x over previous
#include <cuda_runtime.h>
#include <cuda_fp16.h>
#include <math.h>
#include <stdint.h>

#define B_SZ 2048
#define KIN  64
#define KOUT 64
#define KH   129

// Scratch (device globals: allocation-free per the rules)
__device__ __align__(256) __half2 g_Xh[(size_t)B_SZ * KH * KIN];   // [b][f][j] ~67 MB
__device__ __align__(256) __half2 g_Yh[(size_t)B_SZ * KH * KOUT];  // [b][f][i] ~67 MB
__device__ __align__(256) __half  g_Bh[(size_t)KH * 16384];        // [f][n][k] ~4.2 MB

// ===========================================================================
// helpers
// ===========================================================================
__device__ __forceinline__ uint32_t smem_to_u32(const void* p) {
    uint32_t a;
    asm("{ .reg .u64 t; cvta.to.shared.u64 t, %1; cvt.u32.u64 %0, t; }" : "=r"(a) : "l"(p));
    return a;
}
__device__ __forceinline__ void cp_async16(uint32_t dst, const void* src) {
    asm volatile("cp.async.cg.shared.global [%0], [%1], 16;" :: "r"(dst), "l"(src));
}
#define CP_COMMIT() asm volatile("cp.async.commit_group;" ::: "memory")
#define CP_WAIT1()  asm volatile("cp.async.wait_group 1;" ::: "memory")

#define LDSM_X4(r0, r1, r2, r3, addr) \
    asm volatile("ldmatrix.sync.aligned.m8n8.x4.shared.b16 {%0,%1,%2,%3}, [%4];" \
        : "=r"(r0), "=r"(r1), "=r"(r2), "=r"(r3) : "r"(addr))

#define HMMA16(d, a, b0v, b1v) \
    asm volatile("mma.sync.aligned.m16n8k16.row.col.f32.f16.f16.f32 " \
        "{%0,%1,%2,%3}, {%4,%5,%6,%7}, {%8,%9}, {%0,%1,%2,%3};" \
        : "+f"((d)[0]), "+f"((d)[1]), "+f"((d)[2]), "+f"((d)[3]) \
        : "r"((a)[0]), "r"((a)[1]), "r"((a)[2]), "r"((a)[3]), "r"(b0v), "r"(b1v))

__device__ __forceinline__ float2 cmul(float2 a, float2 b) {
    return make_float2(a.x * b.x - a.y * b.y, a.x * b.y + a.y * b.x);
}

// ===========================================================================
// Radix-2 DIF FFT machinery (constant twiddles, outputs bit-reversed)
// ===========================================================================
#define FC1 0.9238795325112867f
#define FS1 0.3826834323650898f
#define FC2 0.7071067811865476f
#define BF(i, j, cr, ci) {                                   \
    float ux = a[i].x, uy = a[i].y;                          \
    float vx = a[j].x, vy = a[j].y;                          \
    a[i].x = ux + vx; a[i].y = uy + vy;                      \
    float dx = ux - vx, dy = uy - vy;                        \
    a[j].x = dx * (cr) - dy * (ci);                          \
    a[j].y = dx * (ci) + dy * (cr); }

template<bool INV>
__device__ __forceinline__ void fft16_full(float2* a) {
    const float S = INV ? 1.0f : -1.0f;
    BF(0, 8, 1.0f, 0.0f)      BF(1, 9, FC1, S * FS1)
    BF(2, 10, FC2, S * FC2)   BF(3, 11, FS1, S * FC1)
    BF(4, 12, 0.0f, S)        BF(5, 13, -FS1, S * FC1)
    BF(6, 14, -FC2, S * FC2)  BF(7, 15, -FC1, S * FS1)
    BF(0, 4, 1.0f, 0.0f)   BF(1, 5, FC2, S * FC2)
    BF(2, 6, 0.0f, S)      BF(3, 7, -FC2, S * FC2)
    BF(8, 12, 1.0f, 0.0f)  BF(9, 13, FC2, S * FC2)
    BF(10, 14, 0.0f, S)    BF(11, 15, -FC2, S * FC2)
    BF(0, 2, 1.0f, 0.0f)   BF(1, 3, 0.0f, S)
    BF(4, 6, 1.0f, 0.0f)   BF(5, 7, 0.0f, S)
    BF(8, 10, 1.0f, 0.0f)  BF(9, 11, 0.0f, S)
    BF(12, 14, 1.0f, 0.0f) BF(13, 15, 0.0f, S)
    BF(0, 1, 1.0f, 0.0f)   BF(2, 3, 1.0f, 0.0f)
    BF(4, 5, 1.0f, 0.0f)   BF(6, 7, 1.0f, 0.0f)
    BF(8, 9, 1.0f, 0.0f)   BF(10, 11, 1.0f, 0.0f)
    BF(12, 13, 1.0f, 0.0f) BF(14, 15, 1.0f, 0.0f)
}
template<bool INV>
__device__ __forceinline__ void fft8(float2* a) {
    const float S = INV ? 1.0f : -1.0f;
    BF(0, 4, 1.0f, 0.0f)  BF(1, 5, FC2, S * FC2)
    BF(2, 6, 0.0f, S)     BF(3, 7, -FC2, S * FC2)
    BF(0, 2, 1.0f, 0.0f)  BF(1, 3, 0.0f, S)
    BF(4, 6, 1.0f, 0.0f)  BF(5, 7, 0.0f, S)
    BF(0, 1, 1.0f, 0.0f)  BF(2, 3, 1.0f, 0.0f)
    BF(4, 5, 1.0f, 0.0f)  BF(6, 7, 1.0f, 0.0f)
}
#define REV4_LIST {0, 8, 4, 12, 2, 10, 6, 14, 1, 9, 5, 13, 3, 11, 7, 15}
#define REV3_LIST {0, 4, 2, 6, 1, 5, 3, 7}

// Bank-swizzled slot layout for the 128-pt working set (float2 units)
#define QP 257
#define SLOT(q, blk, m1) ((q) * QP + ((blk) << 3) + ((m1) ^ ((blk) & 7)))
#define FFT_SMEM (2048 + 16 * QP * 8)   // 34944 B

// ---------------------------------------------------------------------------
// Kernel 1: build B_f[n][k] half (2x-expanded complex conj W)
// ---------------------------------------------------------------------------
__global__ void prep_b(const float* __restrict__ Wr, const float* __restrict__ Wi) {
    int idx = blockIdx.x * blockDim.x + threadIdx.x;
    if (idx >= KH * 16384) return;
    int k = idx & 127;
    int n = (idx >> 7) & 127;
    int f = idx >> 14;
    int j = k >> 1, p = k & 1;
    int i = n >> 1, q = n & 1;
    size_t widx = ((size_t)i * KIN + j) * KH + f;
    float v;
    if (p == 0) v = (q == 0) ? Wr[widx] : -Wi[widx];
    else        v = (q == 0) ? Wi[widx] :  Wr[widx];
    g_Bh[idx] = __float2half_rn(v);
}

// ---------------------------------------------------------------------------
// Kernel 2: forward rFFT via 128-pt complex FFT (z[m]=x[2m]+ix[2m+1]).
// Fused stage-B+unpack with paired columns.
// ---------------------------------------------------------------------------
__global__ __launch_bounds__(256, 4) void fft_fwd(const float* __restrict__ x) {
    extern __shared__ char sm[];
    float2* tw = (float2*)(sm);
    float2* sA = (float2*)(sm + 2048);

    const int rev4[16] = REV4_LIST;
    const int rev3[8]  = REV3_LIST;
    int tid = threadIdx.x;
    {
        float s, c;
        sincospif(-(float)tid * (1.0f / 128.0f), &s, &c);
        tw[tid] = make_float2(c, s);
    }
    int b  = blockIdx.x >> 1;
    int j0 = (blockIdx.x & 1) << 5;

    // Stage A: thread (g2 = block, m1); fft16 over m2 of z[m1+8m2]
    int g2 = tid >> 3;
    int m1 = tid & 7;
    const float2* zp = (const float2*)(x + (size_t)b * 16384 + (size_t)(j0 + g2) * 256);
    float2 a[16];
#pragma unroll
    for (int m2 = 0; m2 < 16; m2++) a[m2] = zp[m1 + 8 * m2];
    __syncthreads(); // tw ready

    fft16_full<false>(a);
#pragma unroll
    for (int q = 0; q < 16; q++) {
        float2 t2 = tw[(2 * m1 * q) & 255]; // W_128^{m1 q}
        sA[SLOT(q, g2, m1)] = cmul(a[rev4[q]], t2);
    }
    __syncthreads();

    // Fused: thread (blk = lane, g = warp): columns qa=g, qb=(g?16-g:8)
    int blk = tid & 31;
    int g   = tid >> 5;
    int qa = g;
    int qb = g ? (16 - g) : 8;

    float2 ca[8], cb[8];
#pragma unroll
    for (int mm = 0; mm < 8; mm++) ca[mm] = sA[SLOT(qa, blk, mm)];
#pragma unroll
    for (int mm = 0; mm < 8; mm++) cb[mm] = sA[SLOT(qb, blk, mm)];
    fft8<false>(ca);   // Z[qa + 16 k1] = ca[rev3[k1]]
    fft8<false>(cb);   // Z[qb + 16 k1] = cb[rev3[k1]]

    __half2* Xcol = g_Xh + (size_t)b * KH * KIN + j0 + blk;
    auto unpack = [&](int kk, float2 Zk, float2 Zm) {
        float2 E = make_float2(0.5f * (Zk.x + Zm.x), 0.5f * (Zk.y - Zm.y));
        float2 O = make_float2(0.5f * (Zk.y + Zm.y), -0.5f * (Zk.x - Zm.x));
        float2 P = cmul(O, tw[kk]);
        Xcol[(size_t)kk * KIN]         = __floats2half2_rn(E.x + P.x, E.y + P.y);
        Xcol[(size_t)(128 - kk) * KIN] = __floats2half2_rn(E.x - P.x, P.y - E.y);
    };

    if (g == 0) {
        unpack(0, ca[0], ca[0]);
#pragma unroll
        for (int t = 1; t < 4; t++) unpack(16 * t, ca[rev3[t]], ca[rev3[8 - t]]);
        unpack(64, ca[rev3[4]], ca[rev3[4]]);
#pragma unroll
        for (int t = 0; t < 4; t++) unpack(8 + 16 * t, cb[rev3[t]], cb[rev3[7 - t]]);
    } else {
#pragma unroll
        for (int t = 0; t < 4; t++) {
            unpack(qa + 16 * t, ca[rev3[t]], cb[rev3[7 - t]]);
            unpack(qb + 16 * t, cb[rev3[t]], ca[rev3[7 - t]]);
        }
    }
}

// ---------------------------------------------------------------------------
// Kernel 3: pipelined fp16 mma.sync GEMM. 4 CTAs per f (4 b-tiles each);
// direct epilogue, 2 syncs per tile.
// ---------------------------------------------------------------------------
#define SMB   0
#define SMA0  (128 * 272)
#define SMA1  (2 * 128 * 272)
#define SMTOT (3 * 128 * 272)
#define NTILES 4

__global__ __launch_bounds__(256, 2) void cgemm_h() {
    extern __shared__ char smem[];
    uint32_t sb = smem_to_u32(smem);
    int f    = blockIdx.x;
    int part = blockIdx.y;
    int tid  = threadIdx.x;

    {
        int r = tid & 127, h = tid >> 7;
        const char* src = (const char*)(g_Bh + (size_t)f * 16384) + r * 256 + h * 128;
        uint32_t dst = sb + SMB + r * 272 + h * 128;
#pragma unroll
        for (int cc = 0; cc < 8; cc++) cp_async16(dst + cc * 16, src + cc * 16);
    }

    auto loadA = [&](int gt, int buf) {   // gt = global b-tile index
        int r = tid & 127, h = tid >> 7;
        const char* src = (const char*)(g_Xh + ((size_t)(gt * 128 + r) * KH + f) * KIN) + h * 128;
        uint32_t dst = sb + (buf ? SMA1 : SMA0) + r * 272 + h * 128;
#pragma unroll
        for (int cc = 0; cc < 8; cc++) cp_async16(dst + cc * 16, src + cc * 16);
    };

    int gt0 = part * NTILES;
    loadA(gt0, 0);
    CP_COMMIT();

    int lane = tid & 31, warp = tid >> 5;
    int wm = warp & 3;
    int wn = warp >> 2;

    int arow = wm * 32 + (lane & 15);
    int acol2 = ((lane >> 4) << 3) * 2;
    uint32_t aoff0 = (uint32_t)(arow * 272 + acol2);
    uint32_t aoff1 = (uint32_t)((arow + 16) * 272 + acol2);
    int brow = wn * 64 + (lane & 7) + ((lane >> 4) << 3);
    int bcol2 = (((lane >> 3) & 1) << 3) * 2;
    uint32_t boff0 = (uint32_t)(brow * 272 + bcol2);

    const int l4 = lane >> 2, lm = lane & 3;

    for (int it = 0; it < NTILES; it++) {
        if (it + 1 < NTILES) loadA(gt0 + it + 1, (it + 1) & 1);
        CP_COMMIT();
        CP_WAIT1();
        __syncthreads();

        uint32_t abase = sb + ((it & 1) ? SMA1 : SMA0);
        uint32_t bbase = sb + SMB;

        float acc[2][8][4];
#pragma unroll
        for (int mt = 0; mt < 2; mt++)
#pragma unroll
            for (int nt = 0; nt < 8; nt++)
#pragma unroll
                for (int r = 0; r < 4; r++) acc[mt][nt][r] = 0.f;

#pragma unroll
        for (int s = 0; s < 8; s++) {
            uint32_t kb = (uint32_t)s * 32;
            uint32_t a0[4], a1[4];
            LDSM_X4(a0[0], a0[1], a0[2], a0[3], abase + aoff0 + kb);
            LDSM_X4(a1[0], a1[1], a1[2], a1[3], abase + aoff1 + kb);
#pragma unroll
            for (int np = 0; np < 4; np++) {
                uint32_t b0, b1, b2, b3;
                LDSM_X4(b0, b1, b2, b3, bbase + boff0 + (uint32_t)np * (16 * 272) + kb);
                HMMA16(acc[0][np * 2],     a0, b0, b1);
                HMMA16(acc[1][np * 2],     a1, b0, b1);
                HMMA16(acc[0][np * 2 + 1], a0, b2, b3);
                HMMA16(acc[1][np * 2 + 1], a1, b2, b3);
            }
        }

        // Direct epilogue: half2 complex writes (sector-combined by L2)
        int b0r = (gt0 + it) * 128;
#pragma unroll
        for (int mt = 0; mt < 2; mt++) {
            int mrow = wm * 32 + mt * 16 + l4;
            size_t base0 = ((size_t)(b0r + mrow) * KH + f) * KOUT;
            size_t base1 = base0 + (size_t)8 * KH * KOUT;
#pragma unroll
            for (int nt = 0; nt < 8; nt++) {
                int i = wn * 32 + nt * 4 + lm;
                g_Yh[base0 + i] = __floats2half2_rn(acc[mt][nt][0], acc[mt][nt][1]);
                g_Yh[base1 + i] = __floats2half2_rn(acc[mt][nt][2], acc[mt][nt][3]);
            }
        }
        __syncthreads(); // A buffer fully consumed before it is refilled
    }
}

// ---------------------------------------------------------------------------
// Kernel 4: inverse rFFT via 128-pt complex IFFT.
// Paired-column fused pack: warp g, lane ig owns columns qa=g, qb=(g?16-g:8);
// each Y row loaded ONCE; E/O shared between Z[k] and Z[128-k].
// ---------------------------------------------------------------------------
__global__ __launch_bounds__(256, 4) void fft_inv(float* __restrict__ out) {
    extern __shared__ char sm[];
    float2* tw = (float2*)(sm);
    float2* sZ = (float2*)(sm + 2048);

    const int rev4[16] = REV4_LIST;
    const int rev3[8]  = REV3_LIST;
    int tid = threadIdx.x;
    {
        float s, c;
        sincospif(-(float)tid * (1.0f / 128.0f), &s, &c);
        tw[tid] = make_float2(c, s);
    }
    int b  = blockIdx.x >> 1;
    int i0 = (blockIdx.x & 1) << 5;
    const __half2* Yrow = g_Yh + (size_t)b * KH * KOUT + i0;
    __syncthreads(); // tw ready

    int ig = tid & 31;
    int g  = tid >> 5;
    int qa = g;
    int qb = g ? (16 - g) : 8;

    // pack pair: from (Yk, Ym) at bin k, produce Z[k] and Z[128-k]
    auto packE = [&](int k, float2 Yk, float2 Ym, float2& zk, float2& zm) {
        float2 E  = make_float2(0.5f * (Yk.x + Ym.x), 0.5f * (Yk.y - Ym.y));
        float2 O2 = make_float2(0.5f * (Yk.x - Ym.x), 0.5f * (Yk.y + Ym.y));
        float2 Wc = tw[k];
        float2 Q  = cmul(O2, make_float2(Wc.x, -Wc.y));
        zk = make_float2(E.x - Q.y, E.y + Q.x);
        zm = make_float2(E.x + Q.y, Q.x - E.y);
    };
    auto ldY = [&](int k) {
        return __half22float2(Yrow[(size_t)k * KOUT + ig]);
    };

    float2 ca[8], cb[8];
    if (g == 0) {
        // column qa=0 (k=16t) and qb=8 (k=8+16t)
        float2 dummy;
        packE(0, ldY(0), ldY(128), ca[0], dummy);             // Z[0] only
#pragma unroll
        for (int t = 1; t < 4; t++)
            packE(16 * t, ldY(16 * t), ldY(128 - 16 * t), ca[t], ca[8 - t]);
        packE(64, ldY(64), ldY(64), ca[4], dummy);            // self-pair
#pragma unroll
        for (int t = 0; t < 4; t++)
            packE(8 + 16 * t, ldY(8 + 16 * t), ldY(120 - 16 * t), cb[t], cb[7 - t]);
    } else {
        // k = qa+16t pairs with column qb index 7-t
#pragma unroll
        for (int t = 0; t < 8; t++) {
            packE(qa + 16 * t, ldY(qa + 16 * t), ldY(qb + 16 * (7 - t)),
                  ca[t], cb[7 - t]);
        }
    }
    fft8<true>(ca);
    fft8<true>(cb);
#pragma unroll
    for (int mm = 0; mm < 8; mm++) {
        float2 ta = tw[(2 * mm * qa) & 255];
        sZ[SLOT(qa, ig, mm)] = cmul(ca[rev3[mm]], make_float2(ta.x, -ta.y));
        float2 tb = tw[(2 * mm * qb) & 255];
        sZ[SLOT(qb, ig, mm)] = cmul(cb[rev3[mm]], make_float2(tb.x, -tb.y));
    }
    __syncthreads();

    // Final phase: inverse fft16 over q; thread = (ig, m1); direct float2 output
    {
        int ig2 = tid >> 3;
        int m1 = tid & 7;
        float2 a[16];
#pragma unroll
        for (int q = 0; q < 16; q++) a[q] = sZ[SLOT(q, ig2, m1)];
        fft16_full<true>(a);

        float2* op = (float2*)(out + (size_t)b * 16384 + (size_t)(i0 + ig2) * 256);
#pragma unroll
        for (int m2 = 0; m2 < 16; m2++) {
            float2 v = a[rev4[m2]];
            op[m1 + 8 * m2] = make_float2(v.x * (1.0f / 128.0f), v.y * (1.0f / 128.0f));
        }
    }
}

// ---------------------------------------------------------------------------
extern "C" void kernel_launch(void* const* d_in, const int* in_sizes, int n_in,
                              void* d_out, int out_size) {
    const float* x  = (const float*)d_in[0];
    const float* Wr = (const float*)d_in[1];
    const float* Wi = (const float*)d_in[2];
    float* out = (float*)d_out;

    cudaFuncSetAttribute(cgemm_h, cudaFuncAttributeMaxDynamicSharedMemorySize, SMTOT);
    cudaFuncSetAttribute(fft_fwd, cudaFuncAttributeMaxDynamicSharedMemorySize, FFT_SMEM);
    cudaFuncSetAttribute(fft_inv, cudaFuncAttributeMaxDynamicSharedMemorySize, FFT_SMEM);

    prep_b<<<(KH * 16384 + 255) / 256, 256>>>(Wr, Wi);
    fft_fwd<<<B_SZ * 2, 256, FFT_SMEM>>>(x);
    cgemm_h<<<dim3(KH, 16 / NTILES), 256, SMTOT>>>();
    fft_inv<<<B_SZ * 2, 256, FFT_SMEM>>>(out);
}

// round 14
// speedup vs baseline: 1.3269x; 1.0801x over previous
#include <cuda_runtime.h>
#include <cuda_fp16.h>
#include <math.h>
#include <stdint.h>

#define B_SZ 2048
#define KIN  64
#define KOUT 64
#define KH   129

// Scratch (device globals: allocation-free per the rules)
__device__ __align__(256) __half2 g_Xh[(size_t)B_SZ * KH * KIN];   // [b][f][j] ~67 MB
__device__ __align__(256) __half2 g_Yh[(size_t)B_SZ * KH * KOUT];  // [b][f][i] ~67 MB
__device__ __align__(256) __half  g_B3h[(size_t)KH * 3 * 4096];    // 3 mats per f, ~3.2 MB

// ===========================================================================
// helpers
// ===========================================================================
__device__ __forceinline__ uint32_t smem_to_u32(const void* p) {
    uint32_t a;
    asm("{ .reg .u64 t; cvta.to.shared.u64 t, %1; cvt.u32.u64 %0, t; }" : "=r"(a) : "l"(p));
    return a;
}
__device__ __forceinline__ void cp_async16(uint32_t dst, const void* src) {
    asm volatile("cp.async.cg.shared.global [%0], [%1], 16;" :: "r"(dst), "l"(src));
}
#define CP_COMMIT() asm volatile("cp.async.commit_group;" ::: "memory")
#define CP_WAIT1()  asm volatile("cp.async.wait_group 1;" ::: "memory")

#define LDSM_X4(r0, r1, r2, r3, addr) \
    asm volatile("ldmatrix.sync.aligned.m8n8.x4.shared.b16 {%0,%1,%2,%3}, [%4];" \
        : "=r"(r0), "=r"(r1), "=r"(r2), "=r"(r3) : "r"(addr))

#define HMMA16(d, a, b0v, b1v) \
    asm volatile("mma.sync.aligned.m16n8k16.row.col.f32.f16.f16.f32 " \
        "{%0,%1,%2,%3}, {%4,%5,%6,%7}, {%8,%9}, {%0,%1,%2,%3};" \
        : "+f"((d)[0]), "+f"((d)[1]), "+f"((d)[2]), "+f"((d)[3]) \
        : "r"((a)[0]), "r"((a)[1]), "r"((a)[2]), "r"((a)[3]), "r"(b0v), "r"(b1v))

__device__ __forceinline__ uint32_t prmtu(uint32_t a, uint32_t b, uint32_t s) {
    uint32_t d;
    asm("prmt.b32 %0, %1, %2, %3;" : "=r"(d) : "r"(a), "r"(b), "r"(s));
    return d;
}
__device__ __forceinline__ uint32_t hadd2u(uint32_t a, uint32_t b) {
    uint32_t d;
    asm("add.rn.f16x2 %0, %1, %2;" : "=r"(d) : "r"(a), "r"(b));
    return d;
}
__device__ __forceinline__ float2 cmul(float2 a, float2 b) {
    return make_float2(a.x * b.x - a.y * b.y, a.x * b.y + a.y * b.x);
}
__device__ __forceinline__ uint32_t h2pack(float a, float b) {
    __half2 h = __floats2half2_rn(a, b);
    return *(uint32_t*)&h;
}

// ===========================================================================
// Radix-2 DIF FFT machinery (constant twiddles, outputs bit-reversed)
// ===========================================================================
#define FC1 0.9238795325112867f
#define FS1 0.3826834323650898f
#define FC2 0.7071067811865476f
#define BF(i, j, cr, ci) {                                   \
    float ux = a[i].x, uy = a[i].y;                          \
    float vx = a[j].x, vy = a[j].y;                          \
    a[i].x = ux + vx; a[i].y = uy + vy;                      \
    float dx = ux - vx, dy = uy - vy;                        \
    a[j].x = dx * (cr) - dy * (ci);                          \
    a[j].y = dx * (ci) + dy * (cr); }

template<bool INV>
__device__ __forceinline__ void fft16_full(float2* a) {
    const float S = INV ? 1.0f : -1.0f;
    BF(0, 8, 1.0f, 0.0f)      BF(1, 9, FC1, S * FS1)
    BF(2, 10, FC2, S * FC2)   BF(3, 11, FS1, S * FC1)
    BF(4, 12, 0.0f, S)        BF(5, 13, -FS1, S * FC1)
    BF(6, 14, -FC2, S * FC2)  BF(7, 15, -FC1, S * FS1)
    BF(0, 4, 1.0f, 0.0f)   BF(1, 5, FC2, S * FC2)
    BF(2, 6, 0.0f, S)      BF(3, 7, -FC2, S * FC2)
    BF(8, 12, 1.0f, 0.0f)  BF(9, 13, FC2, S * FC2)
    BF(10, 14, 0.0f, S)    BF(11, 15, -FC2, S * FC2)
    BF(0, 2, 1.0f, 0.0f)   BF(1, 3, 0.0f, S)
    BF(4, 6, 1.0f, 0.0f)   BF(5, 7, 0.0f, S)
    BF(8, 10, 1.0f, 0.0f)  BF(9, 11, 0.0f, S)
    BF(12, 14, 1.0f, 0.0f) BF(13, 15, 0.0f, S)
    BF(0, 1, 1.0f, 0.0f)   BF(2, 3, 1.0f, 0.0f)
    BF(4, 5, 1.0f, 0.0f)   BF(6, 7, 1.0f, 0.0f)
    BF(8, 9, 1.0f, 0.0f)   BF(10, 11, 1.0f, 0.0f)
    BF(12, 13, 1.0f, 0.0f) BF(14, 15, 1.0f, 0.0f)
}
template<bool INV>
__device__ __forceinline__ void fft8(float2* a) {
    const float S = INV ? 1.0f : -1.0f;
    BF(0, 4, 1.0f, 0.0f)  BF(1, 5, FC2, S * FC2)
    BF(2, 6, 0.0f, S)     BF(3, 7, -FC2, S * FC2)
    BF(0, 2, 1.0f, 0.0f)  BF(1, 3, 0.0f, S)
    BF(4, 6, 1.0f, 0.0f)  BF(5, 7, 0.0f, S)
    BF(0, 1, 1.0f, 0.0f)  BF(2, 3, 1.0f, 0.0f)
    BF(4, 5, 1.0f, 0.0f)  BF(6, 7, 1.0f, 0.0f)
}
#define REV4_LIST {0, 8, 4, 12, 2, 10, 6, 14, 1, 9, 5, 13, 3, 11, 7, 15}
#define REV3_LIST {0, 4, 2, 6, 1, 5, 3, 7}

// Bank-swizzled slot layout for the 128-pt working set (float2 units)
#define QP 257
#define SLOT(q, blk, m1) ((q) * QP + ((blk) << 3) + ((m1) ^ ((blk) & 7)))
#define FFT_SMEM (2048 + 16 * QP * 8)   // 34944 B

// ---------------------------------------------------------------------------
// Kernel 1: build 3M B matrices per f, k-permuted for fragment pairing.
//   mat0 = Wr ; mat1 = Wi - Wr ; mat2 = -(Wr + Wi)
//   column p within each 16-chunk stores j = 16*kk + pi(p)
// ---------------------------------------------------------------------------
__global__ void prep_b3(const float* __restrict__ Wr, const float* __restrict__ Wi) {
    int idx = blockIdx.x * blockDim.x + threadIdx.x;
    if (idx >= KH * 3 * 4096) return;
    int col = idx & 63;
    int i   = (idx >> 6) & 63;
    int mat = (idx >> 12) % 3;
    int f   = idx / (3 * 4096);
    int kk = col >> 4, p = col & 15;
    int pi = (p < 8) ? ((p & 1) ? (p >> 1) + 4 : (p >> 1))
                     : ((p & 1) ? ((p - 8) >> 1) + 12 : ((p - 8) >> 1) + 8);
    int j = (kk << 4) + pi;
    size_t widx = ((size_t)i * KIN + j) * KH + f;
    float wr = Wr[widx], wi = Wi[widx];
    float v = (mat == 0) ? wr : (mat == 1) ? (wi - wr) : (-(wr + wi));
    g_B3h[idx] = __float2half_rn(v);
}

// ---------------------------------------------------------------------------
// Kernel 2: forward rFFT via 128-pt complex FFT (z[m]=x[2m]+ix[2m+1]).
// ---------------------------------------------------------------------------
__global__ __launch_bounds__(256, 4) void fft_fwd(const float* __restrict__ x) {
    extern __shared__ char sm[];
    float2* tw = (float2*)(sm);
    float2* sA = (float2*)(sm + 2048);

    const int rev4[16] = REV4_LIST;
    const int rev3[8]  = REV3_LIST;
    int tid = threadIdx.x;
    {
        float s, c;
        sincospif(-(float)tid * (1.0f / 128.0f), &s, &c);
        tw[tid] = make_float2(c, s);
    }
    int b  = blockIdx.x >> 1;
    int j0 = (blockIdx.x & 1) << 5;

    int g2 = tid >> 3;
    int m1 = tid & 7;
    const float2* zp = (const float2*)(x + (size_t)b * 16384 + (size_t)(j0 + g2) * 256);
    float2 a[16];
#pragma unroll
    for (int m2 = 0; m2 < 16; m2++) a[m2] = zp[m1 + 8 * m2];
    __syncthreads(); // tw ready

    fft16_full<false>(a);
#pragma unroll
    for (int q = 0; q < 16; q++) {
        float2 t2 = tw[(2 * m1 * q) & 255];
        sA[SLOT(q, g2, m1)] = cmul(a[rev4[q]], t2);
    }
    __syncthreads();

    int blk = tid & 31;
    int g   = tid >> 5;
    int qa = g;
    int qb = g ? (16 - g) : 8;

    float2 ca[8], cb[8];
#pragma unroll
    for (int mm = 0; mm < 8; mm++) ca[mm] = sA[SLOT(qa, blk, mm)];
#pragma unroll
    for (int mm = 0; mm < 8; mm++) cb[mm] = sA[SLOT(qb, blk, mm)];
    fft8<false>(ca);
    fft8<false>(cb);

    __half2* Xcol = g_Xh + (size_t)b * KH * KIN + j0 + blk;
    auto unpack = [&](int kk, float2 Zk, float2 Zm) {
        float2 E = make_float2(0.5f * (Zk.x + Zm.x), 0.5f * (Zk.y - Zm.y));
        float2 O = make_float2(0.5f * (Zk.y + Zm.y), -0.5f * (Zk.x - Zm.x));
        float2 P = cmul(O, tw[kk]);
        Xcol[(size_t)kk * KIN]         = __floats2half2_rn(E.x + P.x, E.y + P.y);
        Xcol[(size_t)(128 - kk) * KIN] = __floats2half2_rn(E.x - P.x, P.y - E.y);
    };

    if (g == 0) {
        unpack(0, ca[0], ca[0]);
#pragma unroll
        for (int t = 1; t < 4; t++) unpack(16 * t, ca[rev3[t]], ca[rev3[8 - t]]);
        unpack(64, ca[rev3[4]], ca[rev3[4]]);
#pragma unroll
        for (int t = 0; t < 4; t++) unpack(8 + 16 * t, cb[rev3[t]], cb[rev3[7 - t]]);
    } else {
#pragma unroll
        for (int t = 0; t < 4; t++) {
            unpack(qa + 16 * t, ca[rev3[t]], cb[rev3[7 - t]]);
            unpack(qb + 16 * t, cb[rev3[t]], ca[rev3[7 - t]]);
        }
    }
}

// ---------------------------------------------------------------------------
// Kernel 3: 3M complex GEMM (fp16 mma.sync). 4 CTAs per f, 4 b-tiles each.
// acc_a = m1 - m3 = Re; acc_b = m1 + m2 = Im.
// ---------------------------------------------------------------------------
#define SMB3  0
#define B3PITCH 144                   // 64 halfs + 8 pad
#define B3MAT  (64 * B3PITCH)         // 9216
#define SMA0  (3 * B3MAT)             // 27648
#define SMA1  (SMA0 + 128 * 272)
#define SMTOT (SMA0 + 2 * 128 * 272)  // 97280
#define NTILES 4

__global__ __launch_bounds__(256, 2) void cgemm_h() {
    extern __shared__ char smem[];
    uint32_t sb = smem_to_u32(smem);
    int f    = blockIdx.x;
    int part = blockIdx.y;
    int tid  = threadIdx.x;

    // Stage B3 (3 mats, pitched)
    {
        const char* srcb = (const char*)(g_B3h + (size_t)f * 3 * 4096);
        for (int c = tid; c < 1536; c += 256) {
            int mat = c >> 9, rem = c & 511, i = rem >> 3, k16 = rem & 7;
            cp_async16(sb + SMB3 + mat * B3MAT + i * B3PITCH + k16 * 16,
                       srcb + (mat * 4096 + i * 64) * 2 + k16 * 16);
        }
    }

    auto loadA = [&](int gt, int buf) {
        int r = tid & 127, h = tid >> 7;
        const char* src = (const char*)(g_Xh + ((size_t)(gt * 128 + r) * KH + f) * KIN) + h * 128;
        uint32_t dst = sb + (buf ? SMA1 : SMA0) + r * 272 + h * 128;
#pragma unroll
        for (int cc = 0; cc < 8; cc++) cp_async16(dst + cc * 16, src + cc * 16);
    };

    int gt0 = part * NTILES;
    loadA(gt0, 0);
    CP_COMMIT();

    int lane = tid & 31, warp = tid >> 5;
    int wm = warp & 3;    // m 4x32
    int wn = warp >> 2;   // i 2x32

    int arow = wm * 32 + (lane & 15);
    int acol2 = ((lane >> 4) << 3) * 2;
    uint32_t aoff0 = (uint32_t)(arow * 272 + acol2);
    uint32_t aoff1 = (uint32_t)((arow + 16) * 272 + acol2);

    // B LDSM offsets: per mat, per 16-row half of the warp's i32 range
    int brow0 = wn * 32 + (lane & 7) + ((lane >> 4) << 3);
    int bcb   = ((lane >> 3) & 1) * 16;
    uint32_t bo[3][2];
#pragma unroll
    for (int m = 0; m < 3; m++) {
        bo[m][0] = (uint32_t)(m * B3MAT + brow0 * B3PITCH + bcb);
        bo[m][1] = (uint32_t)(m * B3MAT + (brow0 + 16) * B3PITCH + bcb);
    }

    const int gid = lane >> 2, tig = lane & 3;

    for (int it = 0; it < NTILES; it++) {
        if (it + 1 < NTILES) loadA(gt0 + it + 1, (it + 1) & 1);
        CP_COMMIT();
        CP_WAIT1();
        __syncthreads();

        uint32_t abase = sb + ((it & 1) ? SMA1 : SMA0);
        uint32_t bbase = sb + SMB3;

        float acc_a[2][4][4], acc_b[2][4][4];
#pragma unroll
        for (int mt = 0; mt < 2; mt++)
#pragma unroll
            for (int nt = 0; nt < 4; nt++)
#pragma unroll
                for (int r = 0; r < 4; r++) acc_a[mt][nt][r] = 0.f;

        // ---- Loop 1: acc_a = m1 = Xs · M1 (mat0)
#pragma unroll
        for (int kk = 0; kk < 4; kk++) {
            uint32_t kbA = (uint32_t)kk * 64;
            uint32_t xs[2][4];
#pragma unroll
            for (int mt = 0; mt < 2; mt++) {
                uint32_t aoff = mt ? aoff1 : aoff0;
                uint32_t s0[4], s1[4];
                LDSM_X4(s0[0], s0[1], s0[2], s0[3], abase + aoff + kbA);
                LDSM_X4(s1[0], s1[1], s1[2], s1[3], abase + aoff + kbA + 32);
                xs[mt][0] = hadd2u(prmtu(s0[0], s0[2], 0x5410), prmtu(s0[0], s0[2], 0x7632));
                xs[mt][1] = hadd2u(prmtu(s0[1], s0[3], 0x5410), prmtu(s0[1], s0[3], 0x7632));
                xs[mt][2] = hadd2u(prmtu(s1[0], s1[2], 0x5410), prmtu(s1[0], s1[2], 0x7632));
                xs[mt][3] = hadd2u(prmtu(s1[1], s1[3], 0x5410), prmtu(s1[1], s1[3], 0x7632));
            }
            uint32_t t0, t1, t2, t3, t4, t5, t6, t7;
            LDSM_X4(t0, t1, t2, t3, bbase + bo[0][0] + kk * 32);
            LDSM_X4(t4, t5, t6, t7, bbase + bo[0][1] + kk * 32);
#pragma unroll
            for (int mt = 0; mt < 2; mt++) {
                HMMA16(acc_a[mt][0], xs[mt], t0, t1);
                HMMA16(acc_a[mt][1], xs[mt], t2, t3);
                HMMA16(acc_a[mt][2], xs[mt], t4, t5);
                HMMA16(acc_a[mt][3], xs[mt], t6, t7);
            }
        }

        // acc_b = acc_a (= m1)
#pragma unroll
        for (int mt = 0; mt < 2; mt++)
#pragma unroll
            for (int nt = 0; nt < 4; nt++)
#pragma unroll
                for (int r = 0; r < 4; r++) acc_b[mt][nt][r] = acc_a[mt][nt][r];

        // ---- Loop 2: acc_a += Xi·(Wi-Wr) (mat1) ; acc_b += Xr·(-(Wr+Wi)) (mat2)
#pragma unroll
        for (int kk = 0; kk < 4; kk++) {
            uint32_t kbA = (uint32_t)kk * 64;
            uint32_t xr[2][4], xi[2][4];
#pragma unroll
            for (int mt = 0; mt < 2; mt++) {
                uint32_t aoff = mt ? aoff1 : aoff0;
                uint32_t s0[4], s1[4];
                LDSM_X4(s0[0], s0[1], s0[2], s0[3], abase + aoff + kbA);
                LDSM_X4(s1[0], s1[1], s1[2], s1[3], abase + aoff + kbA + 32);
                xr[mt][0] = prmtu(s0[0], s0[2], 0x5410); xi[mt][0] = prmtu(s0[0], s0[2], 0x7632);
                xr[mt][1] = prmtu(s0[1], s0[3], 0x5410); xi[mt][1] = prmtu(s0[1], s0[3], 0x7632);
                xr[mt][2] = prmtu(s1[0], s1[2], 0x5410); xi[mt][2] = prmtu(s1[0], s1[2], 0x7632);
                xr[mt][3] = prmtu(s1[1], s1[3], 0x5410); xi[mt][3] = prmtu(s1[1], s1[3], 0x7632);
            }
            uint32_t u0, u1, u2, u3, u4, u5, u6, u7;
            uint32_t v0, v1, v2, v3, v4, v5, v6, v7;
            LDSM_X4(u0, u1, u2, u3, bbase + bo[1][0] + kk * 32);
            LDSM_X4(u4, u5, u6, u7, bbase + bo[1][1] + kk * 32);
            LDSM_X4(v0, v1, v2, v3, bbase + bo[2][0] + kk * 32);
            LDSM_X4(v4, v5, v6, v7, bbase + bo[2][1] + kk * 32);
#pragma unroll
            for (int mt = 0; mt < 2; mt++) {
                HMMA16(acc_a[mt][0], xi[mt], u0, u1);
                HMMA16(acc_a[mt][1], xi[mt], u2, u3);
                HMMA16(acc_a[mt][2], xi[mt], u4, u5);
                HMMA16(acc_a[mt][3], xi[mt], u6, u7);
                HMMA16(acc_b[mt][0], xr[mt], v0, v1);
                HMMA16(acc_b[mt][1], xr[mt], v2, v3);
                HMMA16(acc_b[mt][2], xr[mt], v4, v5);
                HMMA16(acc_b[mt][3], xr[mt], v6, v7);
            }
        }

        // Epilogue: (Re, Im) half2 pairs, 8B stores
        int b0r = (gt0 + it) * 128;
#pragma unroll
        for (int mt = 0; mt < 2; mt++) {
            int mrow = wm * 32 + mt * 16 + gid;
            size_t base0 = ((size_t)(b0r + mrow) * KH + f) * KOUT;
            size_t base1 = base0 + (size_t)8 * KH * KOUT;
#pragma unroll
            for (int nt = 0; nt < 4; nt++) {
                int i = wn * 32 + nt * 8 + 2 * tig;
                uint2 w0, w1;
                w0.x = h2pack(acc_a[mt][nt][0], acc_b[mt][nt][0]);
                w0.y = h2pack(acc_a[mt][nt][1], acc_b[mt][nt][1]);
                w1.x = h2pack(acc_a[mt][nt][2], acc_b[mt][nt][2]);
                w1.y = h2pack(acc_a[mt][nt][3], acc_b[mt][nt][3]);
                *(uint2*)(g_Yh + base0 + i) = w0;
                *(uint2*)(g_Yh + base1 + i) = w1;
            }
        }
        __syncthreads(); // A buffer fully consumed before it is refilled
    }
}

// ---------------------------------------------------------------------------
// Kernel 4: inverse rFFT via 128-pt complex IFFT (paired-column fused pack).
// ---------------------------------------------------------------------------
__global__ __launch_bounds__(256, 4) void fft_inv(float* __restrict__ out) {
    extern __shared__ char sm[];
    float2* tw = (float2*)(sm);
    float2* sZ = (float2*)(sm + 2048);

    const int rev4[16] = REV4_LIST;
    const int rev3[8]  = REV3_LIST;
    int tid = threadIdx.x;
    {
        float s, c;
        sincospif(-(float)tid * (1.0f / 128.0f), &s, &c);
        tw[tid] = make_float2(c, s);
    }
    int b  = blockIdx.x >> 1;
    int i0 = (blockIdx.x & 1) << 5;
    const __half2* Yrow = g_Yh + (size_t)b * KH * KOUT + i0;
    __syncthreads(); // tw ready

    int ig = tid & 31;
    int g  = tid >> 5;
    int qa = g;
    int qb = g ? (16 - g) : 8;

    auto packE = [&](int k, float2 Yk, float2 Ym, float2& zk, float2& zm) {
        float2 E  = make_float2(0.5f * (Yk.x + Ym.x), 0.5f * (Yk.y - Ym.y));
        float2 O2 = make_float2(0.5f * (Yk.x - Ym.x), 0.5f * (Yk.y + Ym.y));
        float2 Wc = tw[k];
        float2 Q  = cmul(O2, make_float2(Wc.x, -Wc.y));
        zk = make_float2(E.x - Q.y, E.y + Q.x);
        zm = make_float2(E.x + Q.y, Q.x - E.y);
    };
    auto ldY = [&](int k) {
        return __half22float2(Yrow[(size_t)k * KOUT + ig]);
    };

    float2 ca[8], cb[8];
    if (g == 0) {
        float2 dummy;
        packE(0, ldY(0), ldY(128), ca[0], dummy);
#pragma unroll
        for (int t = 1; t < 4; t++)
            packE(16 * t, ldY(16 * t), ldY(128 - 16 * t), ca[t], ca[8 - t]);
        packE(64, ldY(64), ldY(64), ca[4], dummy);
#pragma unroll
        for (int t = 0; t < 4; t++)
            packE(8 + 16 * t, ldY(8 + 16 * t), ldY(120 - 16 * t), cb[t], cb[7 - t]);
    } else {
#pragma unroll
        for (int t = 0; t < 8; t++) {
            packE(qa + 16 * t, ldY(qa + 16 * t), ldY(qb + 16 * (7 - t)),
                  ca[t], cb[7 - t]);
        }
    }
    fft8<true>(ca);
    fft8<true>(cb);
#pragma unroll
    for (int mm = 0; mm < 8; mm++) {
        float2 ta = tw[(2 * mm * qa) & 255];
        sZ[SLOT(qa, ig, mm)] = cmul(ca[rev3[mm]], make_float2(ta.x, -ta.y));
        float2 tb = tw[(2 * mm * qb) & 255];
        sZ[SLOT(qb, ig, mm)] = cmul(cb[rev3[mm]], make_float2(tb.x, -tb.y));
    }
    __syncthreads();

    {
        int ig2 = tid >> 3;
        int m1 = tid & 7;
        float2 a[16];
#pragma unroll
        for (int q = 0; q < 16; q++) a[q] = sZ[SLOT(q, ig2, m1)];
        fft16_full<true>(a);

        float2* op = (float2*)(out + (size_t)b * 16384 + (size_t)(i0 + ig2) * 256);
#pragma unroll
        for (int m2 = 0; m2 < 16; m2++) {
            float2 v = a[rev4[m2]];
            op[m1 + 8 * m2] = make_float2(v.x * (1.0f / 128.0f), v.y * (1.0f / 128.0f));
        }
    }
}

// ---------------------------------------------------------------------------
extern "C" void kernel_launch(void* const* d_in, const int* in_sizes, int n_in,
                              void* d_out, int out_size) {
    const float* x  = (const float*)d_in[0];
    const float* Wr = (const float*)d_in[1];
    const float* Wi = (const float*)d_in[2];
    float* out = (float*)d_out;

    cudaFuncSetAttribute(cgemm_h, cudaFuncAttributeMaxDynamicSharedMemorySize, SMTOT);
    cudaFuncSetAttribute(fft_fwd, cudaFuncAttributeMaxDynamicSharedMemorySize, FFT_SMEM);
    cudaFuncSetAttribute(fft_inv, cudaFuncAttributeMaxDynamicSharedMemorySize, FFT_SMEM);

    prep_b3<<<(KH * 3 * 4096 + 255) / 256, 256>>>(Wr, Wi);
    fft_fwd<<<B_SZ * 2, 256, FFT_SMEM>>>(x);
    cgemm_h<<<dim3(KH, 16 / NTILES), 256, SMTOT>>>();
    fft_inv<<<B_SZ * 2, 256, FFT_SMEM>>>(out);
}